// round 11
// baseline (speedup 1.0000x reference)
#include <cuda_runtime.h>
#include <cuda_fp16.h>
#include <cstdint>

static constexpr int NT = 4096;   // tokens
static constexpr int DD = 1024;   // d_in == d_out
static constexpr size_t WW = (size_t)DD * DD;

// ---------------- scratch (__device__ globals: allocation-free rule) --------
__device__ float g_V[(size_t)NT * DD];              // fp32 V from prep epilogue
__device__ float g_S[(size_t)NT * NT];              // fp32 scores

__device__ __half g_xh[(size_t)NT * DD], g_xl[(size_t)NT * DD];
// region 0: W~q (centered) | region 1: W~k (centered) | region 2: Wv^T (uncentered)
__device__ __half g_wh[(size_t)3 * DD * DD], g_wl[(size_t)3 * DD * DD];
__device__ __half g_Th[(size_t)NT * DD], g_Tl[(size_t)NT * DD];           // T~ = x@M~
__device__ __half g_MTh[(size_t)DD * DD], g_MTl[(size_t)DD * DD];         // M~^T
__device__ __half g_Vth[(size_t)DD * NT];                                 // V^T fp16
__device__ __half g_Ph[(size_t)NT * NT];                                  // P fp16

// rank-2 correction scalars
__device__ float g_aq[DD], g_ak[DD];
__device__ float g_rs[NT], g_xak[NT], g_c1[NT], g_c2[NT];

// ---------------- helpers ---------------------------------------------------
__device__ __forceinline__ uint32_t smem_u32(const void* p) {
    uint32_t a;
    asm("{ .reg .u64 t; cvta.to.shared.u64 t, %1; cvt.u32.u64 %0, t; }"
        : "=r"(a) : "l"(p));
    return a;
}

// 128B-row swizzle: XOR 16B-chunk index (bits 4-6) with row%8 (bits 7-9)
#define SWZ(o) ((o) ^ ((((uint32_t)(o)) >> 3) & 0x70))

__device__ __forceinline__ void cp16(uint32_t saddr, const void* gaddr) {
    asm volatile("cp.async.cg.shared.global [%0], [%1], 16;"
                 :: "r"(saddr), "l"(gaddr));
}

__device__ __forceinline__ void ldm_x4(uint32_t* r, uint32_t addr) {
    asm volatile("ldmatrix.sync.aligned.m8n8.x4.shared.b16 {%0,%1,%2,%3}, [%4];"
                 : "=r"(r[0]), "=r"(r[1]), "=r"(r[2]), "=r"(r[3]) : "r"(addr));
}

__device__ __forceinline__ void mma_f16(float* c, const uint32_t* a, const uint32_t* b) {
    asm volatile(
        "mma.sync.aligned.m16n8k16.row.col.f32.f16.f16.f32 "
        "{%0,%1,%2,%3}, {%4,%5,%6,%7}, {%8,%9}, {%0,%1,%2,%3};"
        : "+f"(c[0]), "+f"(c[1]), "+f"(c[2]), "+f"(c[3])
        : "r"(a[0]), "r"(a[1]), "r"(a[2]), "r"(a[3]), "r"(b[0]), "r"(b[1]));
}

__device__ __forceinline__ void split_store_f16(
    __half* H, __half* L, size_t idx, float a, float b)
{
    const __half h0 = __float2half_rn(a);
    const __half h1 = __float2half_rn(b);
    const __half l0 = __float2half_rn(a - __half2float(h0));
    const __half l1 = __float2half_rn(b - __half2float(h1));
    *reinterpret_cast<__half2*>(H + idx) = __halves2half2(h0, h1);
    *reinterpret_cast<__half2*>(L + idx) = __halves2half2(l0, l1);
}

// ---------------------------------------------------------------------------
// Warp-MMA split-fp16 GEMM, BK=64, 3-stage cp.async pipeline.
//  MODE 0 (scores): S~ = Th@x^T + Tl@x^T (2 terms; tiles Th,Tl,xh);
//                   epilogue adds rank-2 correction, scales by alpha; fp32 C.
//  MODE 1 (PV):     C = A@B^T; 1 term; tiles A0,B0; occupancy 2.
//  MODE 2 (prep, fused grid):
//     by <  32: V = x @ Wv  (2 terms: a0b0+a0b1) -> g_V fp32
//     by >= 32: M~^T = W~k @ W~q^T (3 terms) -> g_MTh/g_MTl split
//  MODE 3 (T):      T~ = xh@M~h + xh@M~l (2 terms; tiles xh,MTh,MTl) -> split
// BM=BN=128, BK=64, 256 threads, 2(m)x4(n) warps, 64x32 warp tile.
// ---------------------------------------------------------------------------
static constexpr int TILE_B = 128 * 128;   // 16 KB (128 rows x 64 fp16)

template <int MODE>
__global__ __launch_bounds__(256, (MODE == 1) ? 2 : 1)
void gemm_mma(const __half* __restrict__ A0, const __half* __restrict__ A1,
              const __half* __restrict__ B0, const __half* __restrict__ B1,
              float* __restrict__ C, int M, int N, int K, float alpha)
{
    constexpr int NTILES  = (MODE == 1) ? 2 : (MODE == 2) ? 4 : 3;
    constexpr int STAGE_B = NTILES * TILE_B;
    constexpr int BT0     = (MODE == 0 || MODE == 2) ? 2 : 1;   // B0 tile index

    extern __shared__ char smem[];
    const uint32_t sb = smem_u32(smem);
    const int tid  = threadIdx.x;
    const int wid  = tid >> 5;
    const int lane = tid & 31;

    const bool isM = (MODE == 2) && (blockIdx.y >= 32);   // M~^T region of prep
    const int bm = (MODE == 2 && isM) ? (blockIdx.y - 32) * 128 : blockIdx.y * 128;
    const int bn = blockIdx.x * 128;
    const int wm = (wid >> 2) * 64;
    const int wn = (wid & 3) * 32;

    // term flags
    const bool useA1 = (MODE == 0) || (MODE == 2 && isM);        // a1*b0 term
    constexpr bool useB1 = (MODE == 2) || (MODE == 3);           // a0*b1 term

    const __half* srcs[4];
    int rbs[4];
    if (MODE == 1) {
        srcs[0] = A0; rbs[0] = bm;
        srcs[1] = B0; rbs[1] = bn;
        srcs[2] = nullptr; rbs[2] = 0;
        srcs[3] = nullptr; rbs[3] = 0;
    } else if (MODE == 2) {
        if (isM) {      // A = W~k splits, B = W~q splits (centered, untransposed)
            srcs[0] = g_wh + WW; srcs[1] = g_wl + WW;
            srcs[2] = g_wh;      srcs[3] = g_wl;
        } else {        // A = xh (2-term), B = Wv^T splits
            srcs[0] = g_xh;          srcs[1] = nullptr;
            srcs[2] = g_wh + 2 * WW; srcs[3] = g_wl + 2 * WW;
        }
        rbs[0] = bm; rbs[1] = bm; rbs[2] = bn; rbs[3] = bn;
    } else if (MODE == 0) {          // tiles {Th, Tl, xh}
        srcs[0] = A0; rbs[0] = bm;
        srcs[1] = A1; rbs[1] = bm;
        srcs[2] = B0; rbs[2] = bn;
        srcs[3] = nullptr; rbs[3] = 0;
    } else {                          // MODE 3: tiles {xh, MTh, MTl}
        srcs[0] = A0; rbs[0] = bm;
        srcs[1] = B0; rbs[1] = bn;
        srcs[2] = B1; rbs[2] = bn;
        srcs[3] = nullptr; rbs[3] = 0;
    }

    auto issue = [&](int stage, int kchunk) {
#pragma unroll
        for (int t = 0; t < NTILES; t++) {
            if (MODE == 2 && t == 1 && !isM) continue;   // V region: skip A1 tile
#pragma unroll
            for (int u = 0; u < 4; u++) {
                const int v = tid + 256 * u;            // 0..1023
                const int row = v >> 3, c16 = v & 7;
                const uint32_t o = (uint32_t)(row * 128 + c16 * 16);
                cp16(sb + stage * STAGE_B + t * TILE_B + SWZ(o),
                     srcs[t] + (size_t)(rbs[t] + row) * K + kchunk * 64 + c16 * 8);
            }
        }
        asm volatile("cp.async.commit_group;");
    };

    float acc[4][4][4];
#pragma unroll
    for (int i = 0; i < 4; i++)
#pragma unroll
        for (int j = 0; j < 4; j++)
#pragma unroll
            for (int r = 0; r < 4; r++) acc[i][j][r] = 0.0f;

    const int nc = K / 64;
    issue(0, 0);
    issue(1, 1);

    const int arow   = lane & 15;
    const int achunk = lane >> 4;
    const int bsub   = lane >> 3;
    const int brow   = (lane & 7) + (bsub >> 1) * 8;
    const int bchunk = bsub & 1;

    for (int i = 0; i < nc; i++) {
        if (i < nc - 1) asm volatile("cp.async.wait_group 1;");
        else            asm volatile("cp.async.wait_group 0;");
        __syncthreads();

        if (i + 2 < nc) issue((i + 2) % 3, i + 2);

        const uint32_t base = sb + (i % 3) * STAGE_B;
#pragma unroll
        for (int s = 0; s < 4; s++) {                  // 4 x k16 per BK=64 chunk
            uint32_t a0[4][4], a1[4][4], b0r[4][2], b1r[4][2];
#pragma unroll
            for (int t = 0; t < 4; t++) {
                const uint32_t o =
                    (uint32_t)((wm + t * 16 + arow) * 128 + (s * 2 + achunk) * 16);
                ldm_x4(a0[t], base + SWZ(o));
                if (useA1) ldm_x4(a1[t], base + TILE_B + SWZ(o));
            }
#pragma unroll
            for (int g = 0; g < 2; g++) {
                const uint32_t o =
                    (uint32_t)((wn + g * 16 + brow) * 128 + (s * 2 + bchunk) * 16);
                uint32_t r[4];
                ldm_x4(r, base + BT0 * TILE_B + SWZ(o));
                b0r[2 * g][0] = r[0]; b0r[2 * g][1] = r[1];
                b0r[2 * g + 1][0] = r[2]; b0r[2 * g + 1][1] = r[3];
                if (useB1) {
                    ldm_x4(r, base + (BT0 + 1) * TILE_B + SWZ(o));
                    b1r[2 * g][0] = r[0]; b1r[2 * g][1] = r[1];
                    b1r[2 * g + 1][0] = r[2]; b1r[2 * g + 1][1] = r[3];
                }
            }
#pragma unroll
            for (int mt = 0; mt < 4; mt++)
#pragma unroll
                for (int nt = 0; nt < 4; nt++) {
                    mma_f16(acc[mt][nt], a0[mt], b0r[nt]);
                    if (useB1) mma_f16(acc[mt][nt], a0[mt], b1r[nt]);
                    if (useA1) mma_f16(acc[mt][nt], a1[mt], b0r[nt]);
                }
        }
    }

    // ---- epilogue ----
    const int r0 = bm + wm + (lane >> 2);
    const int c0 = wn + (lane & 3) * 2;

    if (MODE == 2) {
#pragma unroll
        for (int mt = 0; mt < 4; mt++)
#pragma unroll
            for (int nt = 0; nt < 4; nt++) {
                const int row = r0 + mt * 16;
                const int col = bn + c0 + nt * 8;
                const size_t i0 = (size_t)row * DD + col;
                const size_t i1 = (size_t)(row + 8) * DD + col;
                if (isM) {
                    split_store_f16(g_MTh, g_MTl, i0, acc[mt][nt][0], acc[mt][nt][1]);
                    split_store_f16(g_MTh, g_MTl, i1, acc[mt][nt][2], acc[mt][nt][3]);
                } else {
                    *reinterpret_cast<float2*>(g_V + i0) =
                        make_float2(acc[mt][nt][0], acc[mt][nt][1]);
                    *reinterpret_cast<float2*>(g_V + i1) =
                        make_float2(acc[mt][nt][2], acc[mt][nt][3]);
                }
            }
    } else if (MODE == 3) {
#pragma unroll
        for (int mt = 0; mt < 4; mt++)
#pragma unroll
            for (int nt = 0; nt < 4; nt++) {
                const int row = r0 + mt * 16;
                const int col = bn + c0 + nt * 8;
                split_store_f16(g_Th, g_Tl, (size_t)row * DD + col,
                                acc[mt][nt][0], acc[mt][nt][1]);
                split_store_f16(g_Th, g_Tl, (size_t)(row + 8) * DD + col,
                                acc[mt][nt][2], acc[mt][nt][3]);
            }
    } else if (MODE == 0) {
        // s_ij = (acc + rs_j*c1_i + xak_j*c2_i) * alpha
#pragma unroll
        for (int mt = 0; mt < 4; mt++) {
            const int row = r0 + mt * 16;
            const float c1a = g_c1[row],     c2a = g_c2[row];
            const float c1b = g_c1[row + 8], c2b = g_c2[row + 8];
#pragma unroll
            for (int nt = 0; nt < 4; nt++) {
                const int col = bn + c0 + nt * 8;
                const float rs0 = g_rs[col],  rs1 = g_rs[col + 1];
                const float xk0 = g_xak[col], xk1 = g_xak[col + 1];
                *reinterpret_cast<float2*>(C + (size_t)row * N + col) =
                    make_float2((acc[mt][nt][0] + rs0 * c1a + xk0 * c2a) * alpha,
                                (acc[mt][nt][1] + rs1 * c1a + xk1 * c2a) * alpha);
                *reinterpret_cast<float2*>(C + (size_t)(row + 8) * N + col) =
                    make_float2((acc[mt][nt][2] + rs0 * c1b + xk0 * c2b) * alpha,
                                (acc[mt][nt][3] + rs1 * c1b + xk1 * c2b) * alpha);
            }
        }
    } else {
#pragma unroll
        for (int mt = 0; mt < 4; mt++)
#pragma unroll
            for (int nt = 0; nt < 4; nt++) {
                const int row = r0 + mt * 16;
                const int col = bn + c0 + nt * 8;
                *reinterpret_cast<float2*>(C + (size_t)row * N + col) =
                    make_float2(acc[mt][nt][0] * alpha, acc[mt][nt][1] * alpha);
                *reinterpret_cast<float2*>(C + (size_t)(row + 8) * N + col) =
                    make_float2(acc[mt][nt][2] * alpha, acc[mt][nt][3] * alpha);
            }
    }
}

// ---------------------------------------------------------------------------
// fused hi/lo fp16 splits: z=0 -> x; z=1 -> Wq-0.5; z=2 -> Wk-0.5
// ---------------------------------------------------------------------------
__global__ __launch_bounds__(256)
void split3_f16(const float* __restrict__ x, const float* __restrict__ wq,
                const float* __restrict__ wk)
{
    const int z = blockIdx.y;
    const float* in = (z == 0) ? x : (z == 1) ? wq : wk;
    __half* hi = (z == 0) ? g_xh : (z == 1) ? g_wh : g_wh + WW;
    __half* lo = (z == 0) ? g_xl : (z == 1) ? g_wl : g_wl + WW;
    const int n = (z == 0) ? NT * DD : DD * DD;
    const float bias = (z == 0) ? 0.0f : 0.5f;

    const int idx = (blockIdx.x * 256 + threadIdx.x) * 2;
    if (idx < n) {
        const float2 v = *reinterpret_cast<const float2*>(in + idx);
        split_store_f16(hi, lo, idx, v.x - bias, v.y - bias);
    }
}

// ---------------------------------------------------------------------------
// fp32 [R,C] -> transposed (hi,lo) fp16 [C,R]   (Wv -> Wv^T, uncentered)
// ---------------------------------------------------------------------------
__global__ __launch_bounds__(256)
void tsplit_f16(const float* __restrict__ in,
                __half* __restrict__ oh, __half* __restrict__ ol, int R, int C)
{
    __shared__ float t[32][33];
    const int bx = blockIdx.x * 32, by = blockIdx.y * 32;
    const int tx = threadIdx.x & 31, ty = threadIdx.x >> 5;
#pragma unroll
    for (int j = 0; j < 32; j += 8)
        t[ty + j][tx] = in[(size_t)(by + ty + j) * C + bx + tx];
    __syncthreads();
#pragma unroll
    for (int j = 0; j < 32; j += 8) {
        const float v = t[tx][ty + j];
        const __half h = __float2half_rn(v);
        const size_t o = (size_t)(bx + ty + j) * R + by + tx;
        oh[o] = h;
        ol[o] = __float2half_rn(v - __half2float(h));
    }
}

// ---------------------------------------------------------------------------
// fp32 [R,C] -> transposed fp16 [C,R], hi only   (V -> V^T)
// ---------------------------------------------------------------------------
__global__ __launch_bounds__(256)
void t_h16(const float* __restrict__ in, __half* __restrict__ oh, int R, int C)
{
    __shared__ float t[32][33];
    const int bx = blockIdx.x * 32, by = blockIdx.y * 32;
    const int tx = threadIdx.x & 31, ty = threadIdx.x >> 5;
#pragma unroll
    for (int j = 0; j < 32; j += 8)
        t[ty + j][tx] = in[(size_t)(by + ty + j) * C + bx + tx];
    __syncthreads();
#pragma unroll
    for (int j = 0; j < 32; j += 8) {
        const float v = t[tx][ty + j];
        oh[(size_t)(bx + ty + j) * R + by + tx] = __float2half_rn(v);
    }
}

// ---------------------------------------------------------------------------
// Correction scalars. wrowsums: aq/ak = row sums of (W - 0.5), fp64 accum.
// xscalars: rs_i = sum(x_i), xaq_i = x_i . aq, xak_i = x_i . ak;
//           c1_i = 256*rs_i + 0.5*xaq_i; c2_i = 0.5*rs_i.
// ---------------------------------------------------------------------------
__global__ __launch_bounds__(256)
void wrowsums(const float* __restrict__ wq, const float* __restrict__ wk)
{
    const int r = blockIdx.x & 1023;
    const bool isq = blockIdx.x < 1024;
    const float* src = (isq ? wq : wk) + (size_t)r * DD;
    const int tid = threadIdx.x;

    double s = 0.0;
    for (int c = tid; c < DD; c += 256) s += (double)src[c] - 0.5;

    __shared__ double red[256];
    red[tid] = s;
    __syncthreads();
#pragma unroll
    for (int k = 128; k > 0; k >>= 1) {
        if (tid < k) red[tid] += red[tid + k];
        __syncthreads();
    }
    if (tid == 0) (isq ? g_aq : g_ak)[r] = (float)red[0];
}

__global__ __launch_bounds__(256)
void xscalars(const float* __restrict__ x)
{
    const int i = blockIdx.x;
    const float* p = x + (size_t)i * DD;
    const int tid = threadIdx.x;

    double s0 = 0.0, s1 = 0.0, s2 = 0.0;
    for (int d = tid; d < DD; d += 256) {
        const double xv = p[d];
        s0 += xv;
        s1 += xv * (double)g_aq[d];
        s2 += xv * (double)g_ak[d];
    }
    __shared__ double r0[256], r1[256], r2[256];
    r0[tid] = s0; r1[tid] = s1; r2[tid] = s2;
    __syncthreads();
#pragma unroll
    for (int k = 128; k > 0; k >>= 1) {
        if (tid < k) { r0[tid] += r0[tid + k]; r1[tid] += r1[tid + k]; r2[tid] += r2[tid + k]; }
        __syncthreads();
    }
    if (tid == 0) {
        g_rs[i]  = (float)r0[0];
        g_xak[i] = (float)r2[0];
        g_c1[i]  = (float)(256.0 * r0[0] + 0.5 * r1[0]);
        g_c2[i]  = (float)(0.5 * r0[0]);
    }
}

// ---------------------------------------------------------------------------
// Row softmax over S[4096][4096] -> P fp16 (exp-skip retained)
// ---------------------------------------------------------------------------
__global__ __launch_bounds__(256)
void softmax_f16(const float* __restrict__ S, __half* __restrict__ Ph)
{
    const int row = blockIdx.x;
    const float* p = S + (size_t)row * NT;
    const int tid = threadIdx.x;
    const int base = tid * 16;

    float v[16];
#pragma unroll
    for (int q = 0; q < 4; q++) {
        const float4 x4 = *reinterpret_cast<const float4*>(p + base + q * 4);
        v[q * 4 + 0] = x4.x; v[q * 4 + 1] = x4.y; v[q * 4 + 2] = x4.z; v[q * 4 + 3] = x4.w;
    }

    __shared__ float red[256];
    float tmax = v[0];
#pragma unroll
    for (int q = 1; q < 16; q++) tmax = fmaxf(tmax, v[q]);
    red[tid] = tmax;
    __syncthreads();
#pragma unroll
    for (int s = 128; s > 0; s >>= 1) {
        if (tid < s) red[tid] = fmaxf(red[tid], red[tid + s]);
        __syncthreads();
    }
    const float m = red[0];
    __syncthreads();

    const float cut = m - 20.0f;
    const bool active = (tmax >= cut);

    float sum = 0.0f;
    if (active) {
#pragma unroll
        for (int q = 0; q < 16; q++) {
            v[q] = (v[q] >= cut) ? __expf(v[q] - m) : 0.0f;
            sum += v[q];
        }
    }
    red[tid] = sum;
    __syncthreads();
#pragma unroll
    for (int s = 128; s > 0; s >>= 1) {
        if (tid < s) red[tid] += red[tid + s];
        __syncthreads();
    }
    const float inv = 1.0f / red[0];

    __half* ph = Ph + (size_t)row * NT + base;
    if (active) {
#pragma unroll
        for (int q = 0; q < 8; q++) {
            *reinterpret_cast<__half2*>(ph + 2 * q) =
                __floats2half2_rn(v[2 * q] * inv, v[2 * q + 1] * inv);
        }
    } else {
        const __half2 z = __floats2half2_rn(0.0f, 0.0f);
#pragma unroll
        for (int q = 0; q < 8; q++)
            *reinterpret_cast<__half2*>(ph + 2 * q) = z;
    }
}

// ---------------------------------------------------------------------------
// kernel_launch
// ---------------------------------------------------------------------------
extern "C" void kernel_launch(void* const* d_in, const int* in_sizes, int n_in,
                              void* d_out, int out_size)
{
    const float* x  = (const float*)d_in[0];
    const float* wq = (const float*)d_in[1];
    const float* wk = (const float*)d_in[2];
    const float* wv = (const float*)d_in[3];
    float* out = (float*)d_out;

    float *V, *S;
    __half *xh, *xl, *wh, *wl, *Th, *Tl, *MTh, *MTl, *Vth, *Ph;
    cudaGetSymbolAddress((void**)&V, g_V);
    cudaGetSymbolAddress((void**)&S, g_S);
    cudaGetSymbolAddress((void**)&xh, g_xh);
    cudaGetSymbolAddress((void**)&xl, g_xl);
    cudaGetSymbolAddress((void**)&wh, g_wh);
    cudaGetSymbolAddress((void**)&wl, g_wl);
    cudaGetSymbolAddress((void**)&Th, g_Th);
    cudaGetSymbolAddress((void**)&Tl, g_Tl);
    cudaGetSymbolAddress((void**)&MTh, g_MTh);
    cudaGetSymbolAddress((void**)&MTl, g_MTl);
    cudaGetSymbolAddress((void**)&Vth, g_Vth);
    cudaGetSymbolAddress((void**)&Ph, g_Ph);

    static bool attr_done = false;
    if (!attr_done) {
        cudaFuncSetAttribute(gemm_mma<0>, cudaFuncAttributeMaxDynamicSharedMemorySize,
                             3 * 3 * TILE_B);
        cudaFuncSetAttribute(gemm_mma<1>, cudaFuncAttributeMaxDynamicSharedMemorySize,
                             3 * 2 * TILE_B);
        cudaFuncSetAttribute(gemm_mma<2>, cudaFuncAttributeMaxDynamicSharedMemorySize,
                             3 * 4 * TILE_B);
        cudaFuncSetAttribute(gemm_mma<3>, cudaFuncAttributeMaxDynamicSharedMemorySize,
                             3 * 3 * TILE_B);
        attr_done = true;
    }

    const dim3 blk(256);

    // 1) prep: splits (x uncentered; Wq/Wk centered) + Wv^T split + scalars
    split3_f16<<<dim3(NT * DD / 512, 3), blk>>>(x, wq, wk);
    tsplit_f16<<<dim3(DD / 32, DD / 32), blk>>>(wv, wh + 2 * WW, wl + 2 * WW, DD, DD);
    wrowsums<<<2048, blk>>>(wq, wk);
    xscalars<<<NT, blk>>>(x);

    // 2) fused prep GEMM: V = x@Wv (fp32) and M~^T = W~k@W~q^T (split fp16)
    gemm_mma<2><<<dim3(DD / 128, NT / 128 + DD / 128), blk, 3 * 4 * TILE_B>>>(
        nullptr, nullptr, nullptr, nullptr, nullptr, 0, DD, DD, 1.0f);

    // 3) V^T fp16 (hi only)
    t_h16<<<dim3(DD / 32, NT / 32), blk>>>(V, Vth, NT, DD);

    // 4) T~ = x @ M~  (2-term; split-store Th/Tl)
    gemm_mma<3><<<dim3(DD / 128, NT / 128), blk, 3 * 3 * TILE_B>>>(
        xh, nullptr, MTh, MTl, nullptr, NT, DD, DD, 1.0f);

    // 5) scores: S = (T~ @ x^T + rank-2 corr) / 32   (2-term)
    gemm_mma<0><<<dim3(NT / 128, NT / 128), blk, 3 * 3 * TILE_B>>>(
        Th, Tl, xh, nullptr, S, NT, NT, DD, 1.0f / 32.0f);

    // 6) softmax -> P fp16
    softmax_f16<<<NT, blk>>>(S, Ph);

    // 7) out = P @ V   (1-term; occupancy 2; B = V^T [1024, 4096])
    gemm_mma<1><<<dim3(DD / 128, NT / 128), blk, 3 * 2 * TILE_B>>>(
        Ph, nullptr, Vth, nullptr, out, NT, DD, NT, 1.0f);
}

// round 12
// speedup vs baseline: 1.1501x; 1.1501x over previous
#include <cuda_runtime.h>
#include <cuda_fp16.h>
#include <cstdint>

static constexpr int NT = 4096;   // tokens
static constexpr int DD = 1024;   // d_in == d_out
static constexpr size_t WW = (size_t)DD * DD;

// ---------------- scratch (__device__ globals: allocation-free rule) --------
__device__ float g_V[(size_t)NT * DD];              // fp32 V from prep epilogue
__device__ float g_S[(size_t)NT * NT];              // fp32 scores

__device__ __half g_xh[(size_t)NT * DD], g_xl[(size_t)NT * DD];
// region 0: W~q (centered) | region 1: W~k (centered) | region 2: Wv^T (uncentered)
__device__ __half g_wh[(size_t)3 * DD * DD], g_wl[(size_t)3 * DD * DD];
__device__ __half g_Th[(size_t)NT * DD], g_Tl[(size_t)NT * DD];           // T~ = x@M~
__device__ __half g_MTh[(size_t)DD * DD], g_MTl[(size_t)DD * DD];         // M~^T
__device__ __half g_Vth[(size_t)DD * NT];                                 // V^T fp16
__device__ __half g_Ph[(size_t)NT * NT];                                  // P fp16

// rank-2 correction scalars
__device__ float g_aq[DD], g_ak[DD];
__device__ float g_rs[NT], g_xak[NT], g_c1[NT], g_c2[NT];

// ---------------- helpers ---------------------------------------------------
__device__ __forceinline__ uint32_t smem_u32(const void* p) {
    uint32_t a;
    asm("{ .reg .u64 t; cvta.to.shared.u64 t, %1; cvt.u32.u64 %0, t; }"
        : "=r"(a) : "l"(p));
    return a;
}

// 128B-row swizzle: XOR 16B-chunk index (bits 4-6) with row%8 (bits 7-9)
#define SWZ(o) ((o) ^ ((((uint32_t)(o)) >> 3) & 0x70))

__device__ __forceinline__ void cp16(uint32_t saddr, const void* gaddr) {
    asm volatile("cp.async.cg.shared.global [%0], [%1], 16;"
                 :: "r"(saddr), "l"(gaddr));
}

__device__ __forceinline__ void ldm_x4(uint32_t* r, uint32_t addr) {
    asm volatile("ldmatrix.sync.aligned.m8n8.x4.shared.b16 {%0,%1,%2,%3}, [%4];"
                 : "=r"(r[0]), "=r"(r[1]), "=r"(r[2]), "=r"(r[3]) : "r"(addr));
}

__device__ __forceinline__ void mma_f16(float* c, const uint32_t* a, const uint32_t* b) {
    asm volatile(
        "mma.sync.aligned.m16n8k16.row.col.f32.f16.f16.f32 "
        "{%0,%1,%2,%3}, {%4,%5,%6,%7}, {%8,%9}, {%0,%1,%2,%3};"
        : "+f"(c[0]), "+f"(c[1]), "+f"(c[2]), "+f"(c[3])
        : "r"(a[0]), "r"(a[1]), "r"(a[2]), "r"(a[3]), "r"(b[0]), "r"(b[1]));
}

__device__ __forceinline__ void split_store_f16(
    __half* H, __half* L, size_t idx, float a, float b)
{
    const __half h0 = __float2half_rn(a);
    const __half h1 = __float2half_rn(b);
    const __half l0 = __float2half_rn(a - __half2float(h0));
    const __half l1 = __float2half_rn(b - __half2float(h1));
    *reinterpret_cast<__half2*>(H + idx) = __halves2half2(h0, h1);
    *reinterpret_cast<__half2*>(L + idx) = __halves2half2(l0, l1);
}

// ---------------------------------------------------------------------------
// Warp-MMA split-fp16 GEMM, BK=64, 3-stage cp.async pipeline.
//  MODE 0 (scores): S~ = Th@x^T + Tl@x^T (2 terms; tiles Th,Tl,xh);
//                   epilogue adds rank-2 correction, scales by alpha; fp32 C.
//  MODE 1 (PV):     C = A@B^T; 1 term; tiles A0,B0; occupancy 2.
//  MODE 2 (prep, fused grid):
//     by <  32: V = x @ Wv  (2 terms: a0b0+a0b1) -> g_V fp32
//     by >= 32: M~^T = W~k @ W~q^T (3 terms) -> g_MTh/g_MTl split
//  MODE 3 (T):      T~ = xh@M~h + xh@M~l (2 terms; tiles xh,MTh,MTl) -> split
// BM=BN=128, BK=64, 256 threads, 2(m)x4(n) warps, 64x32 warp tile.
// ---------------------------------------------------------------------------
static constexpr int TILE_B = 128 * 128;   // 16 KB (128 rows x 64 fp16)

template <int MODE>
__global__ __launch_bounds__(256, (MODE == 1) ? 2 : 1)
void gemm_mma(const __half* __restrict__ A0, const __half* __restrict__ A1,
              const __half* __restrict__ B0, const __half* __restrict__ B1,
              float* __restrict__ C, int M, int N, int K, float alpha)
{
    constexpr int NTILES  = (MODE == 1) ? 2 : (MODE == 2) ? 4 : 3;
    constexpr int STAGE_B = NTILES * TILE_B;
    constexpr int BT0     = (MODE == 0 || MODE == 2) ? 2 : 1;   // B0 tile index

    extern __shared__ char smem[];
    const uint32_t sb = smem_u32(smem);
    const int tid  = threadIdx.x;
    const int wid  = tid >> 5;
    const int lane = tid & 31;

    const bool isM = (MODE == 2) && (blockIdx.y >= 32);   // M~^T region of prep
    const int bm = (MODE == 2 && isM) ? (blockIdx.y - 32) * 128 : blockIdx.y * 128;
    const int bn = blockIdx.x * 128;
    const int wm = (wid >> 2) * 64;
    const int wn = (wid & 3) * 32;

    // term flags
    const bool useA1 = (MODE == 0) || (MODE == 2 && isM);        // a1*b0 term
    constexpr bool useB1 = (MODE == 2) || (MODE == 3);           // a0*b1 term

    const __half* srcs[4];
    int rbs[4];
    if (MODE == 1) {
        srcs[0] = A0; rbs[0] = bm;
        srcs[1] = B0; rbs[1] = bn;
        srcs[2] = nullptr; rbs[2] = 0;
        srcs[3] = nullptr; rbs[3] = 0;
    } else if (MODE == 2) {
        if (isM) {      // A = W~k splits, B = W~q splits (centered, untransposed)
            srcs[0] = g_wh + WW; srcs[1] = g_wl + WW;
            srcs[2] = g_wh;      srcs[3] = g_wl;
        } else {        // A = xh (2-term), B = Wv^T splits
            srcs[0] = g_xh;          srcs[1] = nullptr;
            srcs[2] = g_wh + 2 * WW; srcs[3] = g_wl + 2 * WW;
        }
        rbs[0] = bm; rbs[1] = bm; rbs[2] = bn; rbs[3] = bn;
    } else if (MODE == 0) {          // tiles {Th, Tl, xh}
        srcs[0] = A0; rbs[0] = bm;
        srcs[1] = A1; rbs[1] = bm;
        srcs[2] = B0; rbs[2] = bn;
        srcs[3] = nullptr; rbs[3] = 0;
    } else {                          // MODE 3: tiles {xh, MTh, MTl}
        srcs[0] = A0; rbs[0] = bm;
        srcs[1] = B0; rbs[1] = bn;
        srcs[2] = B1; rbs[2] = bn;
        srcs[3] = nullptr; rbs[3] = 0;
    }

    auto issue = [&](int stage, int kchunk) {
#pragma unroll
        for (int t = 0; t < NTILES; t++) {
            if (MODE == 2 && t == 1 && !isM) continue;   // V region: skip A1 tile
#pragma unroll
            for (int u = 0; u < 4; u++) {
                const int v = tid + 256 * u;            // 0..1023
                const int row = v >> 3, c16 = v & 7;
                const uint32_t o = (uint32_t)(row * 128 + c16 * 16);
                cp16(sb + stage * STAGE_B + t * TILE_B + SWZ(o),
                     srcs[t] + (size_t)(rbs[t] + row) * K + kchunk * 64 + c16 * 8);
            }
        }
        asm volatile("cp.async.commit_group;");
    };

    float acc[4][4][4];
#pragma unroll
    for (int i = 0; i < 4; i++)
#pragma unroll
        for (int j = 0; j < 4; j++)
#pragma unroll
            for (int r = 0; r < 4; r++) acc[i][j][r] = 0.0f;

    const int nc = K / 64;
    issue(0, 0);
    issue(1, 1);

    const int arow   = lane & 15;
    const int achunk = lane >> 4;
    const int bsub   = lane >> 3;
    const int brow   = (lane & 7) + (bsub >> 1) * 8;
    const int bchunk = bsub & 1;

    for (int i = 0; i < nc; i++) {
        if (i < nc - 1) asm volatile("cp.async.wait_group 1;");
        else            asm volatile("cp.async.wait_group 0;");
        __syncthreads();

        if (i + 2 < nc) issue((i + 2) % 3, i + 2);

        const uint32_t base = sb + (i % 3) * STAGE_B;
#pragma unroll
        for (int s = 0; s < 4; s++) {                  // 4 x k16 per BK=64 chunk
            uint32_t a0[4][4], a1[4][4], b0r[4][2], b1r[4][2];
#pragma unroll
            for (int t = 0; t < 4; t++) {
                const uint32_t o =
                    (uint32_t)((wm + t * 16 + arow) * 128 + (s * 2 + achunk) * 16);
                ldm_x4(a0[t], base + SWZ(o));
                if (useA1) ldm_x4(a1[t], base + TILE_B + SWZ(o));
            }
#pragma unroll
            for (int g = 0; g < 2; g++) {
                const uint32_t o =
                    (uint32_t)((wn + g * 16 + brow) * 128 + (s * 2 + bchunk) * 16);
                uint32_t r[4];
                ldm_x4(r, base + BT0 * TILE_B + SWZ(o));
                b0r[2 * g][0] = r[0]; b0r[2 * g][1] = r[1];
                b0r[2 * g + 1][0] = r[2]; b0r[2 * g + 1][1] = r[3];
                if (useB1) {
                    ldm_x4(r, base + (BT0 + 1) * TILE_B + SWZ(o));
                    b1r[2 * g][0] = r[0]; b1r[2 * g][1] = r[1];
                    b1r[2 * g + 1][0] = r[2]; b1r[2 * g + 1][1] = r[3];
                }
            }
#pragma unroll
            for (int mt = 0; mt < 4; mt++)
#pragma unroll
                for (int nt = 0; nt < 4; nt++) {
                    mma_f16(acc[mt][nt], a0[mt], b0r[nt]);
                    if (useB1) mma_f16(acc[mt][nt], a0[mt], b1r[nt]);
                    if (useA1) mma_f16(acc[mt][nt], a1[mt], b0r[nt]);
                }
        }
    }

    // ---- epilogue ----
    const int r0 = bm + wm + (lane >> 2);
    const int c0 = wn + (lane & 3) * 2;

    if (MODE == 2) {
#pragma unroll
        for (int mt = 0; mt < 4; mt++)
#pragma unroll
            for (int nt = 0; nt < 4; nt++) {
                const int row = r0 + mt * 16;
                const int col = bn + c0 + nt * 8;
                const size_t i0 = (size_t)row * DD + col;
                const size_t i1 = (size_t)(row + 8) * DD + col;
                if (isM) {
                    split_store_f16(g_MTh, g_MTl, i0, acc[mt][nt][0], acc[mt][nt][1]);
                    split_store_f16(g_MTh, g_MTl, i1, acc[mt][nt][2], acc[mt][nt][3]);
                } else {
                    *reinterpret_cast<float2*>(g_V + i0) =
                        make_float2(acc[mt][nt][0], acc[mt][nt][1]);
                    *reinterpret_cast<float2*>(g_V + i1) =
                        make_float2(acc[mt][nt][2], acc[mt][nt][3]);
                }
            }
    } else if (MODE == 3) {
#pragma unroll
        for (int mt = 0; mt < 4; mt++)
#pragma unroll
            for (int nt = 0; nt < 4; nt++) {
                const int row = r0 + mt * 16;
                const int col = bn + c0 + nt * 8;
                split_store_f16(g_Th, g_Tl, (size_t)row * DD + col,
                                acc[mt][nt][0], acc[mt][nt][1]);
                split_store_f16(g_Th, g_Tl, (size_t)(row + 8) * DD + col,
                                acc[mt][nt][2], acc[mt][nt][3]);
            }
    } else if (MODE == 0) {
        // s_ij = (acc + rs_j*c1_i + xak_j*c2_i) * alpha
#pragma unroll
        for (int mt = 0; mt < 4; mt++) {
            const int row = r0 + mt * 16;
            const float c1a = g_c1[row],     c2a = g_c2[row];
            const float c1b = g_c1[row + 8], c2b = g_c2[row + 8];
#pragma unroll
            for (int nt = 0; nt < 4; nt++) {
                const int col = bn + c0 + nt * 8;
                const float rs0 = g_rs[col],  rs1 = g_rs[col + 1];
                const float xk0 = g_xak[col], xk1 = g_xak[col + 1];
                *reinterpret_cast<float2*>(C + (size_t)row * N + col) =
                    make_float2((acc[mt][nt][0] + rs0 * c1a + xk0 * c2a) * alpha,
                                (acc[mt][nt][1] + rs1 * c1a + xk1 * c2a) * alpha);
                *reinterpret_cast<float2*>(C + (size_t)(row + 8) * N + col) =
                    make_float2((acc[mt][nt][2] + rs0 * c1b + xk0 * c2b) * alpha,
                                (acc[mt][nt][3] + rs1 * c1b + xk1 * c2b) * alpha);
            }
        }
    } else {
#pragma unroll
        for (int mt = 0; mt < 4; mt++)
#pragma unroll
            for (int nt = 0; nt < 4; nt++) {
                const int row = r0 + mt * 16;
                const int col = bn + c0 + nt * 8;
                *reinterpret_cast<float2*>(C + (size_t)row * N + col) =
                    make_float2(acc[mt][nt][0] * alpha, acc[mt][nt][1] * alpha);
                *reinterpret_cast<float2*>(C + (size_t)(row + 8) * N + col) =
                    make_float2(acc[mt][nt][2] * alpha, acc[mt][nt][3] * alpha);
            }
    }
}

// ---------------------------------------------------------------------------
// fused hi/lo fp16 splits: z=0 -> x; z=1 -> Wq-0.5; z=2 -> Wk-0.5
// ---------------------------------------------------------------------------
__global__ __launch_bounds__(256)
void split3_f16(const float* __restrict__ x, const float* __restrict__ wq,
                const float* __restrict__ wk)
{
    const int z = blockIdx.y;
    const float* in = (z == 0) ? x : (z == 1) ? wq : wk;
    __half* hi = (z == 0) ? g_xh : (z == 1) ? g_wh : g_wh + WW;
    __half* lo = (z == 0) ? g_xl : (z == 1) ? g_wl : g_wl + WW;
    const int n = (z == 0) ? NT * DD : DD * DD;
    const float bias = (z == 0) ? 0.0f : 0.5f;

    const int idx = (blockIdx.x * 256 + threadIdx.x) * 2;
    if (idx < n) {
        const float2 v = *reinterpret_cast<const float2*>(in + idx);
        split_store_f16(hi, lo, idx, v.x - bias, v.y - bias);
    }
}

// ---------------------------------------------------------------------------
// fp32 [R,C] -> transposed (hi,lo) fp16 [C,R]   (Wv -> Wv^T, uncentered)
// ---------------------------------------------------------------------------
__global__ __launch_bounds__(256)
void tsplit_f16(const float* __restrict__ in,
                __half* __restrict__ oh, __half* __restrict__ ol, int R, int C)
{
    __shared__ float t[32][33];
    const int bx = blockIdx.x * 32, by = blockIdx.y * 32;
    const int tx = threadIdx.x & 31, ty = threadIdx.x >> 5;
#pragma unroll
    for (int j = 0; j < 32; j += 8)
        t[ty + j][tx] = in[(size_t)(by + ty + j) * C + bx + tx];
    __syncthreads();
#pragma unroll
    for (int j = 0; j < 32; j += 8) {
        const float v = t[tx][ty + j];
        const __half h = __float2half_rn(v);
        const size_t o = (size_t)(bx + ty + j) * R + by + tx;
        oh[o] = h;
        ol[o] = __float2half_rn(v - __half2float(h));
    }
}

// ---------------------------------------------------------------------------
// fp32 [R,C] -> transposed fp16 [C,R], hi only   (V -> V^T)
// ---------------------------------------------------------------------------
__global__ __launch_bounds__(256)
void t_h16(const float* __restrict__ in, __half* __restrict__ oh, int R, int C)
{
    __shared__ float t[32][33];
    const int bx = blockIdx.x * 32, by = blockIdx.y * 32;
    const int tx = threadIdx.x & 31, ty = threadIdx.x >> 5;
#pragma unroll
    for (int j = 0; j < 32; j += 8)
        t[ty + j][tx] = in[(size_t)(by + ty + j) * C + bx + tx];
    __syncthreads();
#pragma unroll
    for (int j = 0; j < 32; j += 8) {
        const float v = t[tx][ty + j];
        oh[(size_t)(bx + ty + j) * R + by + tx] = __float2half_rn(v);
    }
}

// ---------------------------------------------------------------------------
// Correction scalars — fp32 warp-per-row with shuffle reductions.
// wrowsums: aq/ak[r] = sum_c (W[r][c] - 0.5).  2048 warps = 256 blocks.
// xscalars: rs_i = sum(x_i); c1_i = 256*rs_i + 0.5*(x_i.aq); c2_i = 0.5*rs_i;
//           xak_i = x_i.ak.   4096 warps = 512 blocks.
// ---------------------------------------------------------------------------
__global__ __launch_bounds__(256)
void wrowsums(const float* __restrict__ wq, const float* __restrict__ wk)
{
    const int warp = blockIdx.x * 8 + (threadIdx.x >> 5);   // 0..2047
    const int lane = threadIdx.x & 31;
    const int r = warp & 1023;
    const bool isq = warp < 1024;
    const float* src = (isq ? wq : wk) + (size_t)r * DD;

    float s = 0.0f;
#pragma unroll
    for (int it = 0; it < 8; it++) {
        const float4 v = *reinterpret_cast<const float4*>(src + it * 128 + lane * 4);
        s += (v.x - 0.5f) + (v.y - 0.5f) + (v.z - 0.5f) + (v.w - 0.5f);
    }
#pragma unroll
    for (int o = 16; o > 0; o >>= 1) s += __shfl_xor_sync(0xFFFFFFFFu, s, o);
    if (lane == 0) (isq ? g_aq : g_ak)[r] = s;
}

__global__ __launch_bounds__(256)
void xscalars(const float* __restrict__ x)
{
    const int warp = blockIdx.x * 8 + (threadIdx.x >> 5);   // 0..4095
    const int lane = threadIdx.x & 31;
    const float* p = x + (size_t)warp * DD;

    float s0 = 0.0f, s1 = 0.0f, s2 = 0.0f;
#pragma unroll
    for (int it = 0; it < 8; it++) {
        const int d = it * 128 + lane * 4;
        const float4 xv = *reinterpret_cast<const float4*>(p + d);
        const float4 aq = *reinterpret_cast<const float4*>(g_aq + d);
        const float4 ak = *reinterpret_cast<const float4*>(g_ak + d);
        s0 += xv.x + xv.y + xv.z + xv.w;
        s1 += xv.x * aq.x + xv.y * aq.y + xv.z * aq.z + xv.w * aq.w;
        s2 += xv.x * ak.x + xv.y * ak.y + xv.z * ak.z + xv.w * ak.w;
    }
#pragma unroll
    for (int o = 16; o > 0; o >>= 1) {
        s0 += __shfl_xor_sync(0xFFFFFFFFu, s0, o);
        s1 += __shfl_xor_sync(0xFFFFFFFFu, s1, o);
        s2 += __shfl_xor_sync(0xFFFFFFFFu, s2, o);
    }
    if (lane == 0) {
        g_rs[warp]  = s0;
        g_xak[warp] = s2;
        g_c1[warp]  = 256.0f * s0 + 0.5f * s1;
        g_c2[warp]  = 0.5f * s0;
    }
}

// ---------------------------------------------------------------------------
// Row softmax over S[4096][4096] -> P fp16 (exp-skip retained)
// ---------------------------------------------------------------------------
__global__ __launch_bounds__(256)
void softmax_f16(const float* __restrict__ S, __half* __restrict__ Ph)
{
    const int row = blockIdx.x;
    const float* p = S + (size_t)row * NT;
    const int tid = threadIdx.x;
    const int base = tid * 16;

    float v[16];
#pragma unroll
    for (int q = 0; q < 4; q++) {
        const float4 x4 = *reinterpret_cast<const float4*>(p + base + q * 4);
        v[q * 4 + 0] = x4.x; v[q * 4 + 1] = x4.y; v[q * 4 + 2] = x4.z; v[q * 4 + 3] = x4.w;
    }

    __shared__ float red[256];
    float tmax = v[0];
#pragma unroll
    for (int q = 1; q < 16; q++) tmax = fmaxf(tmax, v[q]);
    red[tid] = tmax;
    __syncthreads();
#pragma unroll
    for (int s = 128; s > 0; s >>= 1) {
        if (tid < s) red[tid] = fmaxf(red[tid], red[tid + s]);
        __syncthreads();
    }
    const float m = red[0];
    __syncthreads();

    const float cut = m - 20.0f;
    const bool active = (tmax >= cut);

    float sum = 0.0f;
    if (active) {
#pragma unroll
        for (int q = 0; q < 16; q++) {
            v[q] = (v[q] >= cut) ? __expf(v[q] - m) : 0.0f;
            sum += v[q];
        }
    }
    red[tid] = sum;
    __syncthreads();
#pragma unroll
    for (int s = 128; s > 0; s >>= 1) {
        if (tid < s) red[tid] += red[tid + s];
        __syncthreads();
    }
    const float inv = 1.0f / red[0];

    __half* ph = Ph + (size_t)row * NT + base;
    if (active) {
#pragma unroll
        for (int q = 0; q < 8; q++) {
            *reinterpret_cast<__half2*>(ph + 2 * q) =
                __floats2half2_rn(v[2 * q] * inv, v[2 * q + 1] * inv);
        }
    } else {
        const __half2 z = __floats2half2_rn(0.0f, 0.0f);
#pragma unroll
        for (int q = 0; q < 8; q++)
            *reinterpret_cast<__half2*>(ph + 2 * q) = z;
    }
}

// ---------------------------------------------------------------------------
// kernel_launch
// ---------------------------------------------------------------------------
extern "C" void kernel_launch(void* const* d_in, const int* in_sizes, int n_in,
                              void* d_out, int out_size)
{
    const float* x  = (const float*)d_in[0];
    const float* wq = (const float*)d_in[1];
    const float* wk = (const float*)d_in[2];
    const float* wv = (const float*)d_in[3];
    float* out = (float*)d_out;

    float *V, *S;
    __half *xh, *xl, *wh, *wl, *Th, *Tl, *MTh, *MTl, *Vth, *Ph;
    cudaGetSymbolAddress((void**)&V, g_V);
    cudaGetSymbolAddress((void**)&S, g_S);
    cudaGetSymbolAddress((void**)&xh, g_xh);
    cudaGetSymbolAddress((void**)&xl, g_xl);
    cudaGetSymbolAddress((void**)&wh, g_wh);
    cudaGetSymbolAddress((void**)&wl, g_wl);
    cudaGetSymbolAddress((void**)&Th, g_Th);
    cudaGetSymbolAddress((void**)&Tl, g_Tl);
    cudaGetSymbolAddress((void**)&MTh, g_MTh);
    cudaGetSymbolAddress((void**)&MTl, g_MTl);
    cudaGetSymbolAddress((void**)&Vth, g_Vth);
    cudaGetSymbolAddress((void**)&Ph, g_Ph);

    static bool attr_done = false;
    if (!attr_done) {
        cudaFuncSetAttribute(gemm_mma<0>, cudaFuncAttributeMaxDynamicSharedMemorySize,
                             3 * 3 * TILE_B);
        cudaFuncSetAttribute(gemm_mma<1>, cudaFuncAttributeMaxDynamicSharedMemorySize,
                             3 * 2 * TILE_B);
        cudaFuncSetAttribute(gemm_mma<2>, cudaFuncAttributeMaxDynamicSharedMemorySize,
                             3 * 4 * TILE_B);
        cudaFuncSetAttribute(gemm_mma<3>, cudaFuncAttributeMaxDynamicSharedMemorySize,
                             3 * 3 * TILE_B);
        attr_done = true;
    }

    const dim3 blk(256);

    // 1) prep: splits (x uncentered; Wq/Wk centered) + Wv^T split + scalars
    split3_f16<<<dim3(NT * DD / 512, 3), blk>>>(x, wq, wk);
    tsplit_f16<<<dim3(DD / 32, DD / 32), blk>>>(wv, wh + 2 * WW, wl + 2 * WW, DD, DD);
    wrowsums<<<256, blk>>>(wq, wk);
    xscalars<<<512, blk>>>(x);

    // 2) fused prep GEMM: V = x@Wv (fp32) and M~^T = W~k@W~q^T (split fp16)
    gemm_mma<2><<<dim3(DD / 128, NT / 128 + DD / 128), blk, 3 * 4 * TILE_B>>>(
        nullptr, nullptr, nullptr, nullptr, nullptr, 0, DD, DD, 1.0f);

    // 3) V^T fp16 (hi only)
    t_h16<<<dim3(DD / 32, NT / 32), blk>>>(V, Vth, NT, DD);

    // 4) T~ = x @ M~  (2-term; split-store Th/Tl)
    gemm_mma<3><<<dim3(DD / 128, NT / 128), blk, 3 * 3 * TILE_B>>>(
        xh, nullptr, MTh, MTl, nullptr, NT, DD, DD, 1.0f);

    // 5) scores: S = (T~ @ x^T + rank-2 corr) / 32   (2-term)
    gemm_mma<0><<<dim3(NT / 128, NT / 128), blk, 3 * 3 * TILE_B>>>(
        Th, Tl, xh, nullptr, S, NT, NT, DD, 1.0f / 32.0f);

    // 6) softmax -> P fp16
    softmax_f16<<<NT, blk>>>(S, Ph);

    // 7) out = P @ V   (1-term; occupancy 2; B = V^T [1024, 4096])
    gemm_mma<1><<<dim3(DD / 128, NT / 128), blk, 3 * 2 * TILE_B>>>(
        Ph, nullptr, Vth, nullptr, out, NT, DD, NT, 1.0f);
}

// round 13
// speedup vs baseline: 1.3739x; 1.1946x over previous
#include <cuda_runtime.h>
#include <cuda_fp16.h>
#include <cstdint>

static constexpr int NT = 4096;   // tokens
static constexpr int DD = 1024;   // d_in == d_out
static constexpr size_t WW = (size_t)DD * DD;

// ---------------- scratch (__device__ globals: allocation-free rule) --------
__device__ float g_V[(size_t)NT * DD];              // fp32 V from prep epilogue
__device__ float g_S[(size_t)NT * NT];              // fp32 scores

__device__ __half g_xh[(size_t)NT * DD], g_xl[(size_t)NT * DD];
// region 0: W~q (centered) | region 1: W~k (centered) | region 2: Wv^T (uncentered)
__device__ __half g_wh[(size_t)3 * DD * DD], g_wl[(size_t)3 * DD * DD];
__device__ __half g_Th[(size_t)NT * DD];                                  // T~ = x@M~ (hi only)
__device__ __half g_MTh[(size_t)DD * DD], g_MTl[(size_t)DD * DD];         // M~^T
__device__ __half g_Vth[(size_t)DD * NT];                                 // V^T fp16
__device__ __half g_Ph[(size_t)NT * NT];                                  // P fp16

// rank-2 correction scalars
__device__ float g_aq[DD], g_ak[DD];
__device__ float g_rs[NT], g_xak[NT], g_c1[NT], g_c2[NT];

// ---------------- helpers ---------------------------------------------------
__device__ __forceinline__ uint32_t smem_u32(const void* p) {
    uint32_t a;
    asm("{ .reg .u64 t; cvta.to.shared.u64 t, %1; cvt.u32.u64 %0, t; }"
        : "=r"(a) : "l"(p));
    return a;
}

// 128B-row swizzle: XOR 16B-chunk index (bits 4-6) with row%8 (bits 7-9)
#define SWZ(o) ((o) ^ ((((uint32_t)(o)) >> 3) & 0x70))

__device__ __forceinline__ void cp16(uint32_t saddr, const void* gaddr) {
    asm volatile("cp.async.cg.shared.global [%0], [%1], 16;"
                 :: "r"(saddr), "l"(gaddr));
}

__device__ __forceinline__ void ldm_x4(uint32_t* r, uint32_t addr) {
    asm volatile("ldmatrix.sync.aligned.m8n8.x4.shared.b16 {%0,%1,%2,%3}, [%4];"
                 : "=r"(r[0]), "=r"(r[1]), "=r"(r[2]), "=r"(r[3]) : "r"(addr));
}

__device__ __forceinline__ void mma_f16(float* c, const uint32_t* a, const uint32_t* b) {
    asm volatile(
        "mma.sync.aligned.m16n8k16.row.col.f32.f16.f16.f32 "
        "{%0,%1,%2,%3}, {%4,%5,%6,%7}, {%8,%9}, {%0,%1,%2,%3};"
        : "+f"(c[0]), "+f"(c[1]), "+f"(c[2]), "+f"(c[3])
        : "r"(a[0]), "r"(a[1]), "r"(a[2]), "r"(a[3]), "r"(b[0]), "r"(b[1]));
}

__device__ __forceinline__ void split_store_f16(
    __half* H, __half* L, size_t idx, float a, float b)
{
    const __half h0 = __float2half_rn(a);
    const __half h1 = __float2half_rn(b);
    const __half l0 = __float2half_rn(a - __half2float(h0));
    const __half l1 = __float2half_rn(b - __half2float(h1));
    *reinterpret_cast<__half2*>(H + idx) = __halves2half2(h0, h1);
    *reinterpret_cast<__half2*>(L + idx) = __halves2half2(l0, l1);
}

// ---------------------------------------------------------------------------
// Warp-MMA split-fp16 GEMM, BK=64, 3-stage cp.async pipeline.
//  MODE 0 (scores): S = Th@xh^T (1 term; tiles Th,xh); occupancy 2;
//                   epilogue adds rank-2 correction, scales by alpha; fp32 C.
//  MODE 1 (PV):     C = A@B^T; 1 term; tiles A0,B0; occupancy 2.
//  MODE 2 (prep, fused grid):
//     by <  32: V = x @ Wv  (2 terms: a0b0+a0b1) -> g_V fp32
//     by >= 32: M~^T = W~k @ W~q^T (3 terms) -> g_MTh/g_MTl split
//  MODE 3 (T):      T~ = xh@M~h + xh@M~l (2 terms) -> g_Th (hi only)
// BM=BN=128, BK=64, 256 threads, 2(m)x4(n) warps, 64x32 warp tile.
// ---------------------------------------------------------------------------
static constexpr int TILE_B = 128 * 128;   // 16 KB (128 rows x 64 fp16)

template <int MODE>
__global__ __launch_bounds__(256, (MODE == 0 || MODE == 1) ? 2 : 1)
void gemm_mma(const __half* __restrict__ A0, const __half* __restrict__ A1,
              const __half* __restrict__ B0, const __half* __restrict__ B1,
              float* __restrict__ C, int M, int N, int K, float alpha)
{
    constexpr int NTILES  = (MODE == 0 || MODE == 1) ? 2 : (MODE == 2) ? 4 : 3;
    constexpr int STAGE_B = NTILES * TILE_B;
    constexpr int BT0     = (MODE == 2) ? 2 : 1;   // B0 tile index

    extern __shared__ char smem[];
    const uint32_t sb = smem_u32(smem);
    const int tid  = threadIdx.x;
    const int wid  = tid >> 5;
    const int lane = tid & 31;

    const bool isM = (MODE == 2) && (blockIdx.y >= 32);   // M~^T region of prep
    const int bm = (MODE == 2 && isM) ? (blockIdx.y - 32) * 128 : blockIdx.y * 128;
    const int bn = blockIdx.x * 128;
    const int wm = (wid >> 2) * 64;
    const int wn = (wid & 3) * 32;

    // term flags
    const bool useA1 = (MODE == 2 && isM);                       // a1*b0 term
    constexpr bool useB1 = (MODE == 2) || (MODE == 3);           // a0*b1 term

    const __half* srcs[4];
    int rbs[4];
    if (MODE == 0 || MODE == 1) {
        srcs[0] = A0; rbs[0] = bm;
        srcs[1] = B0; rbs[1] = bn;
        srcs[2] = nullptr; rbs[2] = 0;
        srcs[3] = nullptr; rbs[3] = 0;
    } else if (MODE == 2) {
        if (isM) {      // A = W~k splits, B = W~q splits (centered, untransposed)
            srcs[0] = g_wh + WW; srcs[1] = g_wl + WW;
            srcs[2] = g_wh;      srcs[3] = g_wl;
        } else {        // A = xh (2-term), B = Wv^T splits
            srcs[0] = g_xh;          srcs[1] = nullptr;
            srcs[2] = g_wh + 2 * WW; srcs[3] = g_wl + 2 * WW;
        }
        rbs[0] = bm; rbs[1] = bm; rbs[2] = bn; rbs[3] = bn;
    } else {                          // MODE 3: tiles {xh, MTh, MTl}
        srcs[0] = A0; rbs[0] = bm;
        srcs[1] = B0; rbs[1] = bn;
        srcs[2] = B1; rbs[2] = bn;
        srcs[3] = nullptr; rbs[3] = 0;
    }

    auto issue = [&](int stage, int kchunk) {
#pragma unroll
        for (int t = 0; t < NTILES; t++) {
            if (MODE == 2 && t == 1 && !isM) continue;   // V region: skip A1 tile
#pragma unroll
            for (int u = 0; u < 4; u++) {
                const int v = tid + 256 * u;            // 0..1023
                const int row = v >> 3, c16 = v & 7;
                const uint32_t o = (uint32_t)(row * 128 + c16 * 16);
                cp16(sb + stage * STAGE_B + t * TILE_B + SWZ(o),
                     srcs[t] + (size_t)(rbs[t] + row) * K + kchunk * 64 + c16 * 8);
            }
        }
        asm volatile("cp.async.commit_group;");
    };

    float acc[4][4][4];
#pragma unroll
    for (int i = 0; i < 4; i++)
#pragma unroll
        for (int j = 0; j < 4; j++)
#pragma unroll
            for (int r = 0; r < 4; r++) acc[i][j][r] = 0.0f;

    const int nc = K / 64;
    issue(0, 0);
    issue(1, 1);

    const int arow   = lane & 15;
    const int achunk = lane >> 4;
    const int bsub   = lane >> 3;
    const int brow   = (lane & 7) + (bsub >> 1) * 8;
    const int bchunk = bsub & 1;

    for (int i = 0; i < nc; i++) {
        if (i < nc - 1) asm volatile("cp.async.wait_group 1;");
        else            asm volatile("cp.async.wait_group 0;");
        __syncthreads();

        if (i + 2 < nc) issue((i + 2) % 3, i + 2);

        const uint32_t base = sb + (i % 3) * STAGE_B;
#pragma unroll
        for (int s = 0; s < 4; s++) {                  // 4 x k16 per BK=64 chunk
            uint32_t a0[4][4], a1[4][4], b0r[4][2], b1r[4][2];
#pragma unroll
            for (int t = 0; t < 4; t++) {
                const uint32_t o =
                    (uint32_t)((wm + t * 16 + arow) * 128 + (s * 2 + achunk) * 16);
                ldm_x4(a0[t], base + SWZ(o));
                if (useA1) ldm_x4(a1[t], base + TILE_B + SWZ(o));
            }
#pragma unroll
            for (int g = 0; g < 2; g++) {
                const uint32_t o =
                    (uint32_t)((wn + g * 16 + brow) * 128 + (s * 2 + bchunk) * 16);
                uint32_t r[4];
                ldm_x4(r, base + BT0 * TILE_B + SWZ(o));
                b0r[2 * g][0] = r[0]; b0r[2 * g][1] = r[1];
                b0r[2 * g + 1][0] = r[2]; b0r[2 * g + 1][1] = r[3];
                if (useB1) {
                    ldm_x4(r, base + (BT0 + 1) * TILE_B + SWZ(o));
                    b1r[2 * g][0] = r[0]; b1r[2 * g][1] = r[1];
                    b1r[2 * g + 1][0] = r[2]; b1r[2 * g + 1][1] = r[3];
                }
            }
#pragma unroll
            for (int mt = 0; mt < 4; mt++)
#pragma unroll
                for (int nt = 0; nt < 4; nt++) {
                    mma_f16(acc[mt][nt], a0[mt], b0r[nt]);
                    if (useB1) mma_f16(acc[mt][nt], a0[mt], b1r[nt]);
                    if (useA1) mma_f16(acc[mt][nt], a1[mt], b0r[nt]);
                }
        }
    }

    // ---- epilogue ----
    const int r0 = bm + wm + (lane >> 2);
    const int c0 = wn + (lane & 3) * 2;

    if (MODE == 2) {
#pragma unroll
        for (int mt = 0; mt < 4; mt++)
#pragma unroll
            for (int nt = 0; nt < 4; nt++) {
                const int row = r0 + mt * 16;
                const int col = bn + c0 + nt * 8;
                const size_t i0 = (size_t)row * DD + col;
                const size_t i1 = (size_t)(row + 8) * DD + col;
                if (isM) {
                    split_store_f16(g_MTh, g_MTl, i0, acc[mt][nt][0], acc[mt][nt][1]);
                    split_store_f16(g_MTh, g_MTl, i1, acc[mt][nt][2], acc[mt][nt][3]);
                } else {
                    *reinterpret_cast<float2*>(g_V + i0) =
                        make_float2(acc[mt][nt][0], acc[mt][nt][1]);
                    *reinterpret_cast<float2*>(g_V + i1) =
                        make_float2(acc[mt][nt][2], acc[mt][nt][3]);
                }
            }
    } else if (MODE == 3) {
#pragma unroll
        for (int mt = 0; mt < 4; mt++)
#pragma unroll
            for (int nt = 0; nt < 4; nt++) {
                const int row = r0 + mt * 16;
                const int col = bn + c0 + nt * 8;
                *reinterpret_cast<__half2*>(g_Th + (size_t)row * DD + col) =
                    __floats2half2_rn(acc[mt][nt][0], acc[mt][nt][1]);
                *reinterpret_cast<__half2*>(g_Th + (size_t)(row + 8) * DD + col) =
                    __floats2half2_rn(acc[mt][nt][2], acc[mt][nt][3]);
            }
    } else if (MODE == 0) {
        // s_ij = (acc + rs_j*c1_i + xak_j*c2_i) * alpha
#pragma unroll
        for (int mt = 0; mt < 4; mt++) {
            const int row = r0 + mt * 16;
            const float c1a = g_c1[row],     c2a = g_c2[row];
            const float c1b = g_c1[row + 8], c2b = g_c2[row + 8];
#pragma unroll
            for (int nt = 0; nt < 4; nt++) {
                const int col = bn + c0 + nt * 8;
                const float rs0 = g_rs[col],  rs1 = g_rs[col + 1];
                const float xk0 = g_xak[col], xk1 = g_xak[col + 1];
                *reinterpret_cast<float2*>(C + (size_t)row * N + col) =
                    make_float2((acc[mt][nt][0] + rs0 * c1a + xk0 * c2a) * alpha,
                                (acc[mt][nt][1] + rs1 * c1a + xk1 * c2a) * alpha);
                *reinterpret_cast<float2*>(C + (size_t)(row + 8) * N + col) =
                    make_float2((acc[mt][nt][2] + rs0 * c1b + xk0 * c2b) * alpha,
                                (acc[mt][nt][3] + rs1 * c1b + xk1 * c2b) * alpha);
            }
        }
    } else {
#pragma unroll
        for (int mt = 0; mt < 4; mt++)
#pragma unroll
            for (int nt = 0; nt < 4; nt++) {
                const int row = r0 + mt * 16;
                const int col = bn + c0 + nt * 8;
                *reinterpret_cast<float2*>(C + (size_t)row * N + col) =
                    make_float2(acc[mt][nt][0] * alpha, acc[mt][nt][1] * alpha);
                *reinterpret_cast<float2*>(C + (size_t)(row + 8) * N + col) =
                    make_float2(acc[mt][nt][2] * alpha, acc[mt][nt][3] * alpha);
            }
    }
}

// ---------------------------------------------------------------------------
// fused hi/lo fp16 splits: z=0 -> x; z=1 -> Wq-0.5; z=2 -> Wk-0.5
// ---------------------------------------------------------------------------
__global__ __launch_bounds__(256)
void split3_f16(const float* __restrict__ x, const float* __restrict__ wq,
                const float* __restrict__ wk)
{
    const int z = blockIdx.y;
    const float* in = (z == 0) ? x : (z == 1) ? wq : wk;
    __half* hi = (z == 0) ? g_xh : (z == 1) ? g_wh : g_wh + WW;
    __half* lo = (z == 0) ? g_xl : (z == 1) ? g_wl : g_wl + WW;
    const int n = (z == 0) ? NT * DD : DD * DD;
    const float bias = (z == 0) ? 0.0f : 0.5f;

    const int idx = (blockIdx.x * 256 + threadIdx.x) * 2;
    if (idx < n) {
        const float2 v = *reinterpret_cast<const float2*>(in + idx);
        split_store_f16(hi, lo, idx, v.x - bias, v.y - bias);
    }
}

// ---------------------------------------------------------------------------
// fp32 [R,C] -> transposed (hi,lo) fp16 [C,R]   (Wv -> Wv^T, uncentered)
// ---------------------------------------------------------------------------
__global__ __launch_bounds__(256)
void tsplit_f16(const float* __restrict__ in,
                __half* __restrict__ oh, __half* __restrict__ ol, int R, int C)
{
    __shared__ float t[32][33];
    const int bx = blockIdx.x * 32, by = blockIdx.y * 32;
    const int tx = threadIdx.x & 31, ty = threadIdx.x >> 5;
#pragma unroll
    for (int j = 0; j < 32; j += 8)
        t[ty + j][tx] = in[(size_t)(by + ty + j) * C + bx + tx];
    __syncthreads();
#pragma unroll
    for (int j = 0; j < 32; j += 8) {
        const float v = t[tx][ty + j];
        const __half h = __float2half_rn(v);
        const size_t o = (size_t)(bx + ty + j) * R + by + tx;
        oh[o] = h;
        ol[o] = __float2half_rn(v - __half2float(h));
    }
}

// ---------------------------------------------------------------------------
// fp32 [R,C] -> transposed fp16 [C,R], hi only   (V -> V^T)
// ---------------------------------------------------------------------------
__global__ __launch_bounds__(256)
void t_h16(const float* __restrict__ in, __half* __restrict__ oh, int R, int C)
{
    __shared__ float t[32][33];
    const int bx = blockIdx.x * 32, by = blockIdx.y * 32;
    const int tx = threadIdx.x & 31, ty = threadIdx.x >> 5;
#pragma unroll
    for (int j = 0; j < 32; j += 8)
        t[ty + j][tx] = in[(size_t)(by + ty + j) * C + bx + tx];
    __syncthreads();
#pragma unroll
    for (int j = 0; j < 32; j += 8) {
        const float v = t[tx][ty + j];
        oh[(size_t)(bx + ty + j) * R + by + tx] = __float2half_rn(v);
    }
}

// ---------------------------------------------------------------------------
// Correction scalars — fp32 warp-per-row with shuffle reductions.
// ---------------------------------------------------------------------------
__global__ __launch_bounds__(256)
void wrowsums(const float* __restrict__ wq, const float* __restrict__ wk)
{
    const int warp = blockIdx.x * 8 + (threadIdx.x >> 5);   // 0..2047
    const int lane = threadIdx.x & 31;
    const int r = warp & 1023;
    const bool isq = warp < 1024;
    const float* src = (isq ? wq : wk) + (size_t)r * DD;

    float s = 0.0f;
#pragma unroll
    for (int it = 0; it < 8; it++) {
        const float4 v = *reinterpret_cast<const float4*>(src + it * 128 + lane * 4);
        s += (v.x - 0.5f) + (v.y - 0.5f) + (v.z - 0.5f) + (v.w - 0.5f);
    }
#pragma unroll
    for (int o = 16; o > 0; o >>= 1) s += __shfl_xor_sync(0xFFFFFFFFu, s, o);
    if (lane == 0) (isq ? g_aq : g_ak)[r] = s;
}

__global__ __launch_bounds__(256)
void xscalars(const float* __restrict__ x)
{
    const int warp = blockIdx.x * 8 + (threadIdx.x >> 5);   // 0..4095
    const int lane = threadIdx.x & 31;
    const float* p = x + (size_t)warp * DD;

    float s0 = 0.0f, s1 = 0.0f, s2 = 0.0f;
#pragma unroll
    for (int it = 0; it < 8; it++) {
        const int d = it * 128 + lane * 4;
        const float4 xv = *reinterpret_cast<const float4*>(p + d);
        const float4 aq = *reinterpret_cast<const float4*>(g_aq + d);
        const float4 ak = *reinterpret_cast<const float4*>(g_ak + d);
        s0 += xv.x + xv.y + xv.z + xv.w;
        s1 += xv.x * aq.x + xv.y * aq.y + xv.z * aq.z + xv.w * aq.w;
        s2 += xv.x * ak.x + xv.y * ak.y + xv.z * ak.z + xv.w * ak.w;
    }
#pragma unroll
    for (int o = 16; o > 0; o >>= 1) {
        s0 += __shfl_xor_sync(0xFFFFFFFFu, s0, o);
        s1 += __shfl_xor_sync(0xFFFFFFFFu, s1, o);
        s2 += __shfl_xor_sync(0xFFFFFFFFu, s2, o);
    }
    if (lane == 0) {
        g_rs[warp]  = s0;
        g_xak[warp] = s2;
        g_c1[warp]  = 256.0f * s0 + 0.5f * s1;
        g_c2[warp]  = 0.5f * s0;
    }
}

// ---------------------------------------------------------------------------
// Row softmax over S[4096][4096] -> P fp16 (exp-skip retained)
// ---------------------------------------------------------------------------
__global__ __launch_bounds__(256)
void softmax_f16(const float* __restrict__ S, __half* __restrict__ Ph)
{
    const int row = blockIdx.x;
    const float* p = S + (size_t)row * NT;
    const int tid = threadIdx.x;
    const int base = tid * 16;

    float v[16];
#pragma unroll
    for (int q = 0; q < 4; q++) {
        const float4 x4 = *reinterpret_cast<const float4*>(p + base + q * 4);
        v[q * 4 + 0] = x4.x; v[q * 4 + 1] = x4.y; v[q * 4 + 2] = x4.z; v[q * 4 + 3] = x4.w;
    }

    __shared__ float red[256];
    float tmax = v[0];
#pragma unroll
    for (int q = 1; q < 16; q++) tmax = fmaxf(tmax, v[q]);
    red[tid] = tmax;
    __syncthreads();
#pragma unroll
    for (int s = 128; s > 0; s >>= 1) {
        if (tid < s) red[tid] = fmaxf(red[tid], red[tid + s]);
        __syncthreads();
    }
    const float m = red[0];
    __syncthreads();

    const float cut = m - 20.0f;
    const bool active = (tmax >= cut);

    float sum = 0.0f;
    if (active) {
#pragma unroll
        for (int q = 0; q < 16; q++) {
            v[q] = (v[q] >= cut) ? __expf(v[q] - m) : 0.0f;
            sum += v[q];
        }
    }
    red[tid] = sum;
    __syncthreads();
#pragma unroll
    for (int s = 128; s > 0; s >>= 1) {
        if (tid < s) red[tid] += red[tid + s];
        __syncthreads();
    }
    const float inv = 1.0f / red[0];

    __half* ph = Ph + (size_t)row * NT + base;
    if (active) {
#pragma unroll
        for (int q = 0; q < 8; q++) {
            *reinterpret_cast<__half2*>(ph + 2 * q) =
                __floats2half2_rn(v[2 * q] * inv, v[2 * q + 1] * inv);
        }
    } else {
        const __half2 z = __floats2half2_rn(0.0f, 0.0f);
#pragma unroll
        for (int q = 0; q < 8; q++)
            *reinterpret_cast<__half2*>(ph + 2 * q) = z;
    }
}

// ---------------------------------------------------------------------------
// kernel_launch
// ---------------------------------------------------------------------------
extern "C" void kernel_launch(void* const* d_in, const int* in_sizes, int n_in,
                              void* d_out, int out_size)
{
    const float* x  = (const float*)d_in[0];
    const float* wq = (const float*)d_in[1];
    const float* wk = (const float*)d_in[2];
    const float* wv = (const float*)d_in[3];
    float* out = (float*)d_out;

    float *V, *S;
    __half *xh, *xl, *wh, *wl, *Th, *MTh, *MTl, *Vth, *Ph;
    cudaGetSymbolAddress((void**)&V, g_V);
    cudaGetSymbolAddress((void**)&S, g_S);
    cudaGetSymbolAddress((void**)&xh, g_xh);
    cudaGetSymbolAddress((void**)&xl, g_xl);
    cudaGetSymbolAddress((void**)&wh, g_wh);
    cudaGetSymbolAddress((void**)&wl, g_wl);
    cudaGetSymbolAddress((void**)&Th, g_Th);
    cudaGetSymbolAddress((void**)&MTh, g_MTh);
    cudaGetSymbolAddress((void**)&MTl, g_MTl);
    cudaGetSymbolAddress((void**)&Vth, g_Vth);
    cudaGetSymbolAddress((void**)&Ph, g_Ph);

    static bool attr_done = false;
    if (!attr_done) {
        cudaFuncSetAttribute(gemm_mma<0>, cudaFuncAttributeMaxDynamicSharedMemorySize,
                             3 * 2 * TILE_B);
        cudaFuncSetAttribute(gemm_mma<1>, cudaFuncAttributeMaxDynamicSharedMemorySize,
                             3 * 2 * TILE_B);
        cudaFuncSetAttribute(gemm_mma<2>, cudaFuncAttributeMaxDynamicSharedMemorySize,
                             3 * 4 * TILE_B);
        cudaFuncSetAttribute(gemm_mma<3>, cudaFuncAttributeMaxDynamicSharedMemorySize,
                             3 * 3 * TILE_B);
        attr_done = true;
    }

    const dim3 blk(256);

    // 1) prep: splits (x uncentered; Wq/Wk centered) + Wv^T split + scalars
    split3_f16<<<dim3(NT * DD / 512, 3), blk>>>(x, wq, wk);
    tsplit_f16<<<dim3(DD / 32, DD / 32), blk>>>(wv, wh + 2 * WW, wl + 2 * WW, DD, DD);
    wrowsums<<<256, blk>>>(wq, wk);
    xscalars<<<512, blk>>>(x);

    // 2) fused prep GEMM: V = x@Wv (fp32) and M~^T = W~k@W~q^T (split fp16)
    gemm_mma<2><<<dim3(DD / 128, NT / 128 + DD / 128), blk, 3 * 4 * TILE_B>>>(
        nullptr, nullptr, nullptr, nullptr, nullptr, 0, DD, DD, 1.0f);

    // 3) V^T fp16 (hi only)
    t_h16<<<dim3(DD / 32, NT / 32), blk>>>(V, Vth, NT, DD);

    // 4) T~ = x @ M~  (2-term; store Th hi only)
    gemm_mma<3><<<dim3(DD / 128, NT / 128), blk, 3 * 3 * TILE_B>>>(
        xh, nullptr, MTh, MTl, nullptr, NT, DD, DD, 1.0f);

    // 5) scores: S = (Th @ xh^T + rank-2 corr) / 32   (1 term, occ 2)
    gemm_mma<0><<<dim3(NT / 128, NT / 128), blk, 3 * 2 * TILE_B>>>(
        Th, nullptr, xh, nullptr, S, NT, NT, DD, 1.0f / 32.0f);

    // 6) softmax -> P fp16
    softmax_f16<<<NT, blk>>>(S, Ph);

    // 7) out = P @ V   (1-term; occupancy 2; B = V^T [1024, 4096])
    gemm_mma<1><<<dim3(DD / 128, NT / 128), blk, 3 * 2 * TILE_B>>>(
        Ph, nullptr, Vth, nullptr, out, NT, DD, NT, 1.0f);
}

// round 14
// speedup vs baseline: 1.8369x; 1.3370x over previous
#include <cuda_runtime.h>
#include <cuda_fp16.h>
#include <cstdint>

static constexpr int NT = 4096;   // tokens
static constexpr int DD = 1024;   // d_in == d_out
static constexpr size_t WW = (size_t)DD * DD;

// ---------------- scratch (__device__ globals: allocation-free rule) --------
__device__ float g_V[(size_t)NT * DD];              // fp32 V from prep epilogue
__device__ float g_S[(size_t)NT * NT];              // fp32 scores

__device__ __half g_xh[(size_t)NT * DD], g_xl[(size_t)NT * DD];
// region 0: W~q (centered) | region 1: W~k (centered) | region 2: Wv^T hi
__device__ __half g_wh[(size_t)3 * DD * DD];
__device__ __half g_wl[(size_t)2 * DD * DD];        // lo for Wq, Wk only
__device__ __half g_Th[(size_t)NT * DD];            // T~ = x@M~ (hi only)
__device__ __half g_MTh[(size_t)DD * DD];           // M~^T (hi only)
__device__ __half g_Ph[(size_t)NT * NT];            // P fp16

// rank-2 correction scalars
__device__ float g_aq[DD], g_ak[DD];
__device__ float g_rs[NT], g_xak[NT], g_c1[NT], g_c2[NT];

// sparse-PV chunk bookkeeping: 32 row-blocks x 64 K-chunks
__device__ int g_flags[32][64];
__device__ int g_chunks[32][66];
__device__ int g_nchunk[32];

// ---------------- helpers ---------------------------------------------------
__device__ __forceinline__ uint32_t smem_u32(const void* p) {
    uint32_t a;
    asm("{ .reg .u64 t; cvta.to.shared.u64 t, %1; cvt.u32.u64 %0, t; }"
        : "=r"(a) : "l"(p));
    return a;
}

// 128B-row swizzle: XOR 16B-chunk index (bits 4-6) with row%8 (bits 7-9)
#define SWZ(o) ((o) ^ ((((uint32_t)(o)) >> 3) & 0x70))

__device__ __forceinline__ void cp16(uint32_t saddr, const void* gaddr) {
    asm volatile("cp.async.cg.shared.global [%0], [%1], 16;"
                 :: "r"(saddr), "l"(gaddr));
}

__device__ __forceinline__ void ldm_x4(uint32_t* r, uint32_t addr) {
    asm volatile("ldmatrix.sync.aligned.m8n8.x4.shared.b16 {%0,%1,%2,%3}, [%4];"
                 : "=r"(r[0]), "=r"(r[1]), "=r"(r[2]), "=r"(r[3]) : "r"(addr));
}

__device__ __forceinline__ void mma_f16(float* c, const uint32_t* a, const uint32_t* b) {
    asm volatile(
        "mma.sync.aligned.m16n8k16.row.col.f32.f16.f16.f32 "
        "{%0,%1,%2,%3}, {%4,%5,%6,%7}, {%8,%9}, {%0,%1,%2,%3};"
        : "+f"(c[0]), "+f"(c[1]), "+f"(c[2]), "+f"(c[3])
        : "r"(a[0]), "r"(a[1]), "r"(a[2]), "r"(a[3]), "r"(b[0]), "r"(b[1]));
}

__device__ __forceinline__ void split_store_f16(
    __half* H, __half* L, size_t idx, float a, float b)
{
    const __half h0 = __float2half_rn(a);
    const __half h1 = __float2half_rn(b);
    const __half l0 = __float2half_rn(a - __half2float(h0));
    const __half l1 = __float2half_rn(b - __half2float(h1));
    *reinterpret_cast<__half2*>(H + idx) = __halves2half2(h0, h1);
    *reinterpret_cast<__half2*>(L + idx) = __halves2half2(l0, l1);
}

// ---------------------------------------------------------------------------
// Warp-MMA fp16 GEMM, BK=64, 3-stage cp.async pipeline.
//  MODE 0 (scores): S = Th@xh^T (1 term; tiles Th,xh); occ 2;
//                   epilogue adds rank-2 correction, scales by alpha; fp32 C.
//  MODE 1 (PV):     C = Ph@Vth^T, 1 term, SPARSE over active K-chunks; occ 2.
//  MODE 2 (prep, fused grid; occ 1):
//     by <  32: V = xh @ Wvh^T (1 term, tiles 0,2) -> g_V fp32
//     by >= 32: M~^T = W~k @ W~q^T (3 terms, tiles 0..3) -> g_MTh (hi only)
//  MODE 3 (T):      T~ = xh@M~h (1 term; tiles xh,MTh) -> g_Th; occ 2.
// BM=BN=128, BK=64, 256 threads, 2(m)x4(n) warps, 64x32 warp tile.
// ---------------------------------------------------------------------------
static constexpr int TILE_B = 128 * 128;   // 16 KB (128 rows x 64 fp16)

template <int MODE>
__global__ __launch_bounds__(256, (MODE == 2) ? 1 : 2)
void gemm_mma(const __half* __restrict__ A0, const __half* __restrict__ B0,
              float* __restrict__ C, int M, int N, int K, float alpha)
{
    constexpr int NTILES  = (MODE == 2) ? 4 : 2;
    constexpr int STAGE_B = NTILES * TILE_B;
    constexpr int BT0     = (MODE == 2) ? 2 : 1;   // B0 tile index

    extern __shared__ char smem[];
    const uint32_t sb = smem_u32(smem);
    const int tid  = threadIdx.x;
    const int wid  = tid >> 5;
    const int lane = tid & 31;

    const bool isM = (MODE == 2) && (blockIdx.y >= 32);   // M~^T region of prep
    const int bm = (MODE == 2 && isM) ? (blockIdx.y - 32) * 128 : blockIdx.y * 128;
    const int bn = blockIdx.x * 128;
    const int wm = (wid >> 2) * 64;
    const int wn = (wid & 3) * 32;

    // extra emulation terms only in the M~ region of prep
    const bool useX = (MODE == 2) && isM;

    const __half* srcs[4];
    int rbs[4];
    if (MODE == 2) {
        if (isM) {      // A = W~k splits, B = W~q splits (centered, untransposed)
            srcs[0] = g_wh + WW;     srcs[1] = g_wl + WW;
            srcs[2] = g_wh;          srcs[3] = g_wl;
        } else {        // A = xh, B = Wv^T hi
            srcs[0] = g_xh;          srcs[1] = nullptr;
            srcs[2] = g_wh + 2 * WW; srcs[3] = nullptr;
        }
        rbs[0] = bm; rbs[1] = bm; rbs[2] = bn; rbs[3] = bn;
    } else {
        srcs[0] = A0; rbs[0] = bm;
        srcs[1] = B0; rbs[1] = bn;
        srcs[2] = nullptr; rbs[2] = 0;
        srcs[3] = nullptr; rbs[3] = 0;
    }

    auto issue = [&](int stage, int kchunk) {
#pragma unroll
        for (int t = 0; t < NTILES; t++) {
            if (MODE == 2 && !isM && (t == 1 || t == 3)) continue;  // V: skip lo tiles
#pragma unroll
            for (int u = 0; u < 4; u++) {
                const int v = tid + 256 * u;            // 0..1023
                const int row = v >> 3, c16 = v & 7;
                const uint32_t o = (uint32_t)(row * 128 + c16 * 16);
                cp16(sb + stage * STAGE_B + t * TILE_B + SWZ(o),
                     srcs[t] + (size_t)(rbs[t] + row) * K + kchunk * 64 + c16 * 8);
            }
        }
        asm volatile("cp.async.commit_group;");
    };

    float acc[4][4][4];
#pragma unroll
    for (int i = 0; i < 4; i++)
#pragma unroll
        for (int j = 0; j < 4; j++)
#pragma unroll
            for (int r = 0; r < 4; r++) acc[i][j][r] = 0.0f;

    // chunk schedule: MODE 1 uses the sparse per-row-block list; others dense
    const int* cl = (MODE == 1) ? g_chunks[blockIdx.y] : nullptr;
    const int nc  = (MODE == 1) ? g_nchunk[blockIdx.y] : K / 64;

    issue(0, (MODE == 1) ? cl[0] : 0);
    issue(1, (MODE == 1) ? cl[1] : 1);

    const int arow   = lane & 15;
    const int achunk = lane >> 4;
    const int bsub   = lane >> 3;
    const int brow   = (lane & 7) + (bsub >> 1) * 8;
    const int bchunk = bsub & 1;

    for (int i = 0; i < nc; i++) {
        if (i < nc - 1) asm volatile("cp.async.wait_group 1;");
        else            asm volatile("cp.async.wait_group 0;");
        __syncthreads();

        if (i + 2 < nc) issue((i + 2) % 3, (MODE == 1) ? cl[i + 2] : i + 2);

        const uint32_t base = sb + (i % 3) * STAGE_B;
#pragma unroll
        for (int s = 0; s < 4; s++) {                  // 4 x k16 per BK=64 chunk
            uint32_t a0[4][4], a1[4][4], b0r[4][2], b1r[4][2];
#pragma unroll
            for (int t = 0; t < 4; t++) {
                const uint32_t o =
                    (uint32_t)((wm + t * 16 + arow) * 128 + (s * 2 + achunk) * 16);
                ldm_x4(a0[t], base + SWZ(o));
                if (useX) ldm_x4(a1[t], base + TILE_B + SWZ(o));
            }
#pragma unroll
            for (int g = 0; g < 2; g++) {
                const uint32_t o =
                    (uint32_t)((wn + g * 16 + brow) * 128 + (s * 2 + bchunk) * 16);
                uint32_t r[4];
                ldm_x4(r, base + BT0 * TILE_B + SWZ(o));
                b0r[2 * g][0] = r[0]; b0r[2 * g][1] = r[1];
                b0r[2 * g + 1][0] = r[2]; b0r[2 * g + 1][1] = r[3];
                if (useX) {
                    ldm_x4(r, base + (BT0 + 1) * TILE_B + SWZ(o));
                    b1r[2 * g][0] = r[0]; b1r[2 * g][1] = r[1];
                    b1r[2 * g + 1][0] = r[2]; b1r[2 * g + 1][1] = r[3];
                }
            }
#pragma unroll
            for (int mt = 0; mt < 4; mt++)
#pragma unroll
                for (int nt = 0; nt < 4; nt++) {
                    mma_f16(acc[mt][nt], a0[mt], b0r[nt]);
                    if (useX) {
                        mma_f16(acc[mt][nt], a0[mt], b1r[nt]);
                        mma_f16(acc[mt][nt], a1[mt], b0r[nt]);
                    }
                }
        }
    }

    // ---- epilogue ----
    const int r0 = bm + wm + (lane >> 2);
    const int c0 = wn + (lane & 3) * 2;

    if (MODE == 2) {
#pragma unroll
        for (int mt = 0; mt < 4; mt++)
#pragma unroll
            for (int nt = 0; nt < 4; nt++) {
                const int row = r0 + mt * 16;
                const int col = bn + c0 + nt * 8;
                const size_t i0 = (size_t)row * DD + col;
                const size_t i1 = (size_t)(row + 8) * DD + col;
                if (isM) {
                    *reinterpret_cast<__half2*>(g_MTh + i0) =
                        __floats2half2_rn(acc[mt][nt][0], acc[mt][nt][1]);
                    *reinterpret_cast<__half2*>(g_MTh + i1) =
                        __floats2half2_rn(acc[mt][nt][2], acc[mt][nt][3]);
                } else {
                    *reinterpret_cast<float2*>(g_V + i0) =
                        make_float2(acc[mt][nt][0], acc[mt][nt][1]);
                    *reinterpret_cast<float2*>(g_V + i1) =
                        make_float2(acc[mt][nt][2], acc[mt][nt][3]);
                }
            }
    } else if (MODE == 3) {
#pragma unroll
        for (int mt = 0; mt < 4; mt++)
#pragma unroll
            for (int nt = 0; nt < 4; nt++) {
                const int row = r0 + mt * 16;
                const int col = bn + c0 + nt * 8;
                *reinterpret_cast<__half2*>(g_Th + (size_t)row * DD + col) =
                    __floats2half2_rn(acc[mt][nt][0], acc[mt][nt][1]);
                *reinterpret_cast<__half2*>(g_Th + (size_t)(row + 8) * DD + col) =
                    __floats2half2_rn(acc[mt][nt][2], acc[mt][nt][3]);
            }
    } else if (MODE == 0) {
        // s_ij = (acc + rs_j*c1_i + xak_j*c2_i) * alpha
#pragma unroll
        for (int mt = 0; mt < 4; mt++) {
            const int row = r0 + mt * 16;
            const float c1a = g_c1[row],     c2a = g_c2[row];
            const float c1b = g_c1[row + 8], c2b = g_c2[row + 8];
#pragma unroll
            for (int nt = 0; nt < 4; nt++) {
                const int col = bn + c0 + nt * 8;
                const float rs0 = g_rs[col],  rs1 = g_rs[col + 1];
                const float xk0 = g_xak[col], xk1 = g_xak[col + 1];
                *reinterpret_cast<float2*>(C + (size_t)row * N + col) =
                    make_float2((acc[mt][nt][0] + rs0 * c1a + xk0 * c2a) * alpha,
                                (acc[mt][nt][1] + rs1 * c1a + xk1 * c2a) * alpha);
                *reinterpret_cast<float2*>(C + (size_t)(row + 8) * N + col) =
                    make_float2((acc[mt][nt][2] + rs0 * c1b + xk0 * c2b) * alpha,
                                (acc[mt][nt][3] + rs1 * c1b + xk1 * c2b) * alpha);
            }
        }
    } else {   // MODE 1
#pragma unroll
        for (int mt = 0; mt < 4; mt++)
#pragma unroll
            for (int nt = 0; nt < 4; nt++) {
                const int row = r0 + mt * 16;
                const int col = bn + c0 + nt * 8;
                *reinterpret_cast<float2*>(C + (size_t)row * N + col) =
                    make_float2(acc[mt][nt][0], acc[mt][nt][1]);
                *reinterpret_cast<float2*>(C + (size_t)(row + 8) * N + col) =
                    make_float2(acc[mt][nt][2], acc[mt][nt][3]);
            }
    }
}

// ---------------------------------------------------------------------------
// fused hi/lo fp16 splits: z=0 -> x; z=1 -> Wq-0.5; z=2 -> Wk-0.5
// ---------------------------------------------------------------------------
__global__ __launch_bounds__(256)
void split3_f16(const float* __restrict__ x, const float* __restrict__ wq,
                const float* __restrict__ wk)
{
    const int z = blockIdx.y;
    const float* in = (z == 0) ? x : (z == 1) ? wq : wk;
    __half* hi = (z == 0) ? g_xh : (z == 1) ? g_wh : g_wh + WW;
    __half* lo = (z == 0) ? g_xl : (z == 1) ? g_wl : g_wl + WW;
    const int n = (z == 0) ? NT * DD : DD * DD;
    const float bias = (z == 0) ? 0.0f : 0.5f;

    const int idx = (blockIdx.x * 256 + threadIdx.x) * 2;
    if (idx < n) {
        const float2 v = *reinterpret_cast<const float2*>(in + idx);
        split_store_f16(hi, lo, idx, v.x - bias, v.y - bias);
    }
}

// ---------------------------------------------------------------------------
// fp32 [R,C] -> transposed fp16 [C,R], hi only   (Wv -> Wv^T, V -> V^T)
// ---------------------------------------------------------------------------
__global__ __launch_bounds__(256)
void t_h16(const float* __restrict__ in, __half* __restrict__ oh, int R, int C)
{
    __shared__ float t[32][33];
    const int bx = blockIdx.x * 32, by = blockIdx.y * 32;
    const int tx = threadIdx.x & 31, ty = threadIdx.x >> 5;
#pragma unroll
    for (int j = 0; j < 32; j += 8)
        t[ty + j][tx] = in[(size_t)(by + ty + j) * C + bx + tx];
    __syncthreads();
#pragma unroll
    for (int j = 0; j < 32; j += 8) {
        const float v = t[tx][ty + j];
        oh[(size_t)(bx + ty + j) * R + by + tx] = __float2half_rn(v);
    }
}

// ---------------------------------------------------------------------------
// Correction scalars — fp32 warp-per-row with shuffle reductions.
// xscalars also zeroes the sparse-PV flag array (blocks 0..7).
// ---------------------------------------------------------------------------
__global__ __launch_bounds__(256)
void wrowsums(const float* __restrict__ wq, const float* __restrict__ wk)
{
    const int warp = blockIdx.x * 8 + (threadIdx.x >> 5);   // 0..2047
    const int lane = threadIdx.x & 31;
    const int r = warp & 1023;
    const bool isq = warp < 1024;
    const float* src = (isq ? wq : wk) + (size_t)r * DD;

    float s = 0.0f;
#pragma unroll
    for (int it = 0; it < 8; it++) {
        const float4 v = *reinterpret_cast<const float4*>(src + it * 128 + lane * 4);
        s += (v.x - 0.5f) + (v.y - 0.5f) + (v.z - 0.5f) + (v.w - 0.5f);
    }
#pragma unroll
    for (int o = 16; o > 0; o >>= 1) s += __shfl_xor_sync(0xFFFFFFFFu, s, o);
    if (lane == 0) (isq ? g_aq : g_ak)[r] = s;
}

__global__ __launch_bounds__(256)
void xscalars(const float* __restrict__ x)
{
    if (blockIdx.x < 8) {                       // zero sparse-PV flags (2048 ints)
        (&g_flags[0][0])[blockIdx.x * 256 + threadIdx.x] = 0;
    }

    const int warp = blockIdx.x * 8 + (threadIdx.x >> 5);   // 0..4095
    const int lane = threadIdx.x & 31;
    const float* p = x + (size_t)warp * DD;

    float s0 = 0.0f, s1 = 0.0f, s2 = 0.0f;
#pragma unroll
    for (int it = 0; it < 8; it++) {
        const int d = it * 128 + lane * 4;
        const float4 xv = *reinterpret_cast<const float4*>(p + d);
        const float4 aq = *reinterpret_cast<const float4*>(g_aq + d);
        const float4 ak = *reinterpret_cast<const float4*>(g_ak + d);
        s0 += xv.x + xv.y + xv.z + xv.w;
        s1 += xv.x * aq.x + xv.y * aq.y + xv.z * aq.z + xv.w * aq.w;
        s2 += xv.x * ak.x + xv.y * ak.y + xv.z * ak.z + xv.w * ak.w;
    }
#pragma unroll
    for (int o = 16; o > 0; o >>= 1) {
        s0 += __shfl_xor_sync(0xFFFFFFFFu, s0, o);
        s1 += __shfl_xor_sync(0xFFFFFFFFu, s1, o);
        s2 += __shfl_xor_sync(0xFFFFFFFFu, s2, o);
    }
    if (lane == 0) {
        g_rs[warp]  = s0;
        g_xak[warp] = s2;
        g_c1[warp]  = 256.0f * s0 + 0.5f * s1;
        g_c2[warp]  = 0.5f * s0;
    }
}

// ---------------------------------------------------------------------------
// Row softmax over S[4096][4096] -> P fp16, exp-skip + active-chunk flags.
// Thread tid covers cols [16*tid, 16*tid+16) -> K-chunk tid/4.
// ---------------------------------------------------------------------------
__global__ __launch_bounds__(256)
void softmax_f16(const float* __restrict__ S, __half* __restrict__ Ph)
{
    const int row = blockIdx.x;
    const float* p = S + (size_t)row * NT;
    const int tid = threadIdx.x;
    const int base = tid * 16;

    float v[16];
#pragma unroll
    for (int q = 0; q < 4; q++) {
        const float4 x4 = *reinterpret_cast<const float4*>(p + base + q * 4);
        v[q * 4 + 0] = x4.x; v[q * 4 + 1] = x4.y; v[q * 4 + 2] = x4.z; v[q * 4 + 3] = x4.w;
    }

    __shared__ float red[256];
    float tmax = v[0];
#pragma unroll
    for (int q = 1; q < 16; q++) tmax = fmaxf(tmax, v[q]);
    red[tid] = tmax;
    __syncthreads();
#pragma unroll
    for (int s = 128; s > 0; s >>= 1) {
        if (tid < s) red[tid] = fmaxf(red[tid], red[tid + s]);
        __syncthreads();
    }
    const float m = red[0];
    __syncthreads();

    const float cut = m - 20.0f;
    const bool active = (tmax >= cut);

    if (active) g_flags[row >> 7][tid >> 2] = 1;   // idempotent; races benign

    float sum = 0.0f;
    if (active) {
#pragma unroll
        for (int q = 0; q < 16; q++) {
            v[q] = (v[q] >= cut) ? __expf(v[q] - m) : 0.0f;
            sum += v[q];
        }
    }
    red[tid] = sum;
    __syncthreads();
#pragma unroll
    for (int s = 128; s > 0; s >>= 1) {
        if (tid < s) red[tid] += red[tid + s];
        __syncthreads();
    }
    const float inv = 1.0f / red[0];

    __half* ph = Ph + (size_t)row * NT + base;
    if (active) {
#pragma unroll
        for (int q = 0; q < 8; q++) {
            *reinterpret_cast<__half2*>(ph + 2 * q) =
                __floats2half2_rn(v[2 * q] * inv, v[2 * q + 1] * inv);
        }
    } else {
        const __half2 z = __floats2half2_rn(0.0f, 0.0f);
#pragma unroll
        for (int q = 0; q < 8; q++)
            *reinterpret_cast<__half2*>(ph + 2 * q) = z;
    }
}

// ---------------------------------------------------------------------------
// Compact active-chunk flags into per-row-block lists (padded by 2).
// ---------------------------------------------------------------------------
__global__ __launch_bounds__(32)
void compact_chunks()
{
    const int r = blockIdx.x;
    if (threadIdx.x == 0) {
        int c = 0;
#pragma unroll
        for (int i = 0; i < 64; i++)
            if (g_flags[r][i]) g_chunks[r][c++] = i;
        g_nchunk[r] = c;
        const int pad = g_chunks[r][0];
        g_chunks[r][c] = pad;
        g_chunks[r][c + 1] = pad;
    }
}

// ---------------------------------------------------------------------------
// kernel_launch
// ---------------------------------------------------------------------------
extern "C" void kernel_launch(void* const* d_in, const int* in_sizes, int n_in,
                              void* d_out, int out_size)
{
    const float* x  = (const float*)d_in[0];
    const float* wq = (const float*)d_in[1];
    const float* wk = (const float*)d_in[2];
    const float* wv = (const float*)d_in[3];
    float* out = (float*)d_out;

    float *V, *S;
    __half *xh, *wh, *Th, *MTh, *Vth, *Ph;
    cudaGetSymbolAddress((void**)&V, g_V);
    cudaGetSymbolAddress((void**)&S, g_S);
    cudaGetSymbolAddress((void**)&xh, g_xh);
    cudaGetSymbolAddress((void**)&wh, g_wh);
    cudaGetSymbolAddress((void**)&Th, g_Th);
    cudaGetSymbolAddress((void**)&MTh, g_MTh);
    cudaGetSymbolAddress((void**)&Ph, g_Ph);
    // reuse g_wl's tail? no — V^T gets its own region in g_wh+2WW? It's fp16
    // V^T [DD, NT] = 8 MB; store in g_Ph? No — use dedicated buffer: reuse g_xl
    // is unsafe (xl unused after prep? xl IS unused entirely now!). Use g_xl.
    cudaGetSymbolAddress((void**)&Vth, g_xl);   // V^T fp16 lives in g_xl (8 MB, exact fit)

    static bool attr_done = false;
    if (!attr_done) {
        cudaFuncSetAttribute(gemm_mma<0>, cudaFuncAttributeMaxDynamicSharedMemorySize,
                             3 * 2 * TILE_B);
        cudaFuncSetAttribute(gemm_mma<1>, cudaFuncAttributeMaxDynamicSharedMemorySize,
                             3 * 2 * TILE_B);
        cudaFuncSetAttribute(gemm_mma<2>, cudaFuncAttributeMaxDynamicSharedMemorySize,
                             3 * 4 * TILE_B);
        cudaFuncSetAttribute(gemm_mma<3>, cudaFuncAttributeMaxDynamicSharedMemorySize,
                             3 * 2 * TILE_B);
        attr_done = true;
    }

    const dim3 blk(256);

    // 1) prep: splits (x; Wq/Wk centered hi+lo) + Wv^T hi transpose + scalars
    split3_f16<<<dim3(NT * DD / 512, 3), blk>>>(x, wq, wk);
    t_h16<<<dim3(DD / 32, DD / 32), blk>>>(wv, wh + 2 * WW, DD, DD);
    wrowsums<<<256, blk>>>(wq, wk);
    xscalars<<<512, blk>>>(x);

    // 2) fused prep GEMM: V = xh@Wvh^T (fp32) and M~^T = W~k@W~q^T (fp16 hi)
    gemm_mma<2><<<dim3(DD / 128, NT / 128 + DD / 128), blk, 3 * 4 * TILE_B>>>(
        nullptr, nullptr, nullptr, 0, DD, DD, 1.0f);

    // 3) V^T fp16 (hi only) into g_xl
    {
        __half* vt = (__half*)Vth;
        t_h16<<<dim3(DD / 32, NT / 32), blk>>>(V, vt, NT, DD);
    }

    // 4) T~ = xh @ M~h  (1 term)
    gemm_mma<3><<<dim3(DD / 128, NT / 128), blk, 3 * 2 * TILE_B>>>(
        xh, MTh, nullptr, NT, DD, DD, 1.0f);

    // 5) scores: S = (Th @ xh^T + rank-2 corr) / 32   (1 term, occ 2)
    gemm_mma<0><<<dim3(NT / 128, NT / 128), blk, 3 * 2 * TILE_B>>>(
        Th, xh, S, NT, NT, DD, 1.0f / 32.0f);

    // 6) softmax -> P fp16 + active-chunk flags; then compact lists
    softmax_f16<<<NT, blk>>>(S, Ph);
    compact_chunks<<<32, 32>>>();

    // 7) out = P @ V   (1-term; SPARSE chunks; occ 2; B = V^T [1024, 4096])
    gemm_mma<1><<<dim3(DD / 128, NT / 128), blk, 3 * 2 * TILE_B>>>(
        Ph, (const __half*)Vth, out, NT, DD, NT, 1.0f);
}